// round 10
// baseline (speedup 1.0000x reference)
#include <cuda_runtime.h>
#include <cuda_fp16.h>
#include <cstdint>

// Problem constants
constexpr int B_ = 16384;
constexpr int E_ = 1024;
constexpr int H_ = 8;
constexpr int D_ = 128;

// ---------------------------------------------------------------------------
// Scratch (static device globals: allocation-free, graph-capture safe)
// ---------------------------------------------------------------------------
__device__ __half g_AB[2u * B_ * E_];           // [image; signal] fp16   (64 MB)
__device__ __half g_Wq[E_ * E_];
__device__ __half g_Wk[E_ * E_];
__device__ __half g_Wv[E_ * E_];
__device__ __half g_Wo[E_ * E_];
__device__ __half g_Q[(size_t)B_ * E_];         // q proj                 (32 MB)
__device__ __half g_K[(size_t)2 * B_ * E_];     // [k_img; k_sig]         (64 MB)
__device__ __half g_ctx[(size_t)B_ * E_];       //                        (32 MB)
__device__ float  g_fused[(size_t)B_ * E_];     // attn_out + residual    (64 MB)

// ---------------------------------------------------------------------------
// PTX helpers (sm_80-class only: cp.async / ldmatrix / mma.sync)
// ---------------------------------------------------------------------------
__device__ __forceinline__ uint32_t smem_u32(const void* p) {
    return (uint32_t)__cvta_generic_to_shared(p);
}
__device__ __forceinline__ void cp16(uint32_t s, const void* g) {
    asm volatile("cp.async.cg.shared.global [%0], [%1], 16;\n" :: "r"(s), "l"(g));
}
__device__ __forceinline__ void cp_commit() {
    asm volatile("cp.async.commit_group;\n");
}
template <int N>
__device__ __forceinline__ void cp_wait() {
    asm volatile("cp.async.wait_group %0;\n" :: "n"(N));
}
__device__ __forceinline__ void ldmatrix_x4(uint32_t* r, uint32_t addr) {
    asm volatile("ldmatrix.sync.aligned.m8n8.x4.shared.b16 {%0,%1,%2,%3}, [%4];\n"
                 : "=r"(r[0]), "=r"(r[1]), "=r"(r[2]), "=r"(r[3]) : "r"(addr));
}
__device__ __forceinline__ void mma16816(float* c, const uint32_t* a, const uint32_t* b) {
    asm volatile("mma.sync.aligned.m16n8k16.row.col.f32.f16.f16.f32 "
                 "{%0,%1,%2,%3}, {%4,%5,%6,%7}, {%8,%9}, {%0,%1,%2,%3};\n"
                 : "+f"(c[0]), "+f"(c[1]), "+f"(c[2]), "+f"(c[3])
                 : "r"(a[0]), "r"(a[1]), "r"(a[2]), "r"(a[3]), "r"(b[0]), "r"(b[1]));
}

// ---------------------------------------------------------------------------
// Single conversion kernel (inputs fp32->fp16, weights fp32->fp16)
// ---------------------------------------------------------------------------
constexpr int IN4 = (2 * B_ * E_) / 4;        // 8388608
constexpr int W4  = (4 * E_ * E_) / 4;        // 1048576
constexpr int CVT_TOT = IN4 + W4;             // divisible by 256

__global__ void k_convert_all(const float* __restrict__ img, const float* __restrict__ sig,
                              const float* __restrict__ wq, const float* __restrict__ wk,
                              const float* __restrict__ wv, const float* __restrict__ wo) {
    int i = blockIdx.x * blockDim.x + threadIdx.x;
    if (i < IN4) {
        const int n4 = (B_ * E_) / 4;
        float4 v = (i < n4) ? reinterpret_cast<const float4*>(img)[i]
                            : reinterpret_cast<const float4*>(sig)[i - n4];
        __half* dst = g_AB + (size_t)4 * i;
        *reinterpret_cast<__half2*>(dst)     = __floats2half2_rn(v.x, v.y);
        *reinterpret_cast<__half2*>(dst + 2) = __floats2half2_rn(v.z, v.w);
    } else {
        int j = i - IN4;
        const int per = (E_ * E_) / 4;
        int m = j / per;
        int t = j - m * per;
        const float* src;
        __half* dst;
        if (m == 0)      { src = wq; dst = g_Wq; }
        else if (m == 1) { src = wk; dst = g_Wk; }
        else if (m == 2) { src = wv; dst = g_Wv; }
        else             { src = wo; dst = g_Wo; }
        float4 v = reinterpret_cast<const float4*>(src)[t];
        dst += (size_t)4 * t;
        *reinterpret_cast<__half2*>(dst)     = __floats2half2_rn(v.x, v.y);
        *reinterpret_cast<__half2*>(dst + 2) = __floats2half2_rn(v.z, v.w);
    }
}

// ---------------------------------------------------------------------------
// Shared GEMM core: C[*, cl] = A[M,1024] * W[128 rows,1024]^T (NT), fp16->fp32.
// CTA tile 128x128x64, 3-stage cp.async, 8 warps (2M x 4N), warp 64x32.
// EPI=0: half out = acc + bias[cl];  EPI=1: float out = acc + bias + resid
// ---------------------------------------------------------------------------
constexpr int BM = 128, BN = 128, BK = 64, STAGES = 3;
constexpr int KDIM = 1024, KT = KDIM / BK;           // 16
constexpr int LDS = BK + 8;                          // 72 halfs / 144B row
constexpr int A_STG = BM * LDS;                      // 9216 halfs
constexpr int STG   = 2 * A_STG;
constexpr int SMEM_BYTES = STAGES * STG * (int)sizeof(__half);   // 110592

template <int EPI>
__device__ __forceinline__ void gemm_core(
    const __half* __restrict__ A,
    const __half* __restrict__ W,
    __half* __restrict__ outH,
    float* __restrict__ outF,
    const float* __restrict__ bias,
    const float* __restrict__ resid,
    int bm, int ldOut)
{
    extern __shared__ __half smem[];

    const int tid  = threadIdx.x;
    const int warp = tid >> 5;
    const int lane = tid & 31;
    const int wm   = (warp & 1) * 64;
    const int wn   = (warp >> 1) * 32;

    float acc[4][4][4];
#pragma unroll
    for (int i = 0; i < 4; i++)
#pragma unroll
        for (int j = 0; j < 4; j++)
#pragma unroll
            for (int l = 0; l < 4; l++) acc[i][j][l] = 0.f;

    auto load_stage = [&](int stage, int kt) {
        const int k0 = kt * BK;
        __half* sa = smem + stage * STG;
        __half* sb = sa + A_STG;
#pragma unroll
        for (int i = 0; i < 8; i++) {
            int id = tid + i * 256;
            if (id < 1024) {
                int row = id >> 3, seg = id & 7;
                cp16(smem_u32(sa + row * LDS + seg * 8),
                     A + (size_t)(bm + row) * KDIM + k0 + seg * 8);
            } else {
                id -= 1024;
                int row = id >> 3, seg = id & 7;
                cp16(smem_u32(sb + row * LDS + seg * 8),
                     W + (size_t)row * KDIM + k0 + seg * 8);
            }
        }
    };

#pragma unroll
    for (int s = 0; s < STAGES - 1; s++) { load_stage(s, s); cp_commit(); }

    const int a_row = (lane & 15);
    const int a_col = (lane >> 4) * 8;
    const int b_row = ((lane >> 4) << 3) + (lane & 7);
    const int b_col = ((lane >> 3) & 1) * 8;

    for (int kt = 0; kt < KT; kt++) {
        cp_wait<STAGES - 2>();
        __syncthreads();

        if (kt + STAGES - 1 < KT) load_stage((kt + STAGES - 1) % STAGES, kt + STAGES - 1);
        cp_commit();

        const __half* as = smem + (kt % STAGES) * STG;
        const __half* bs = as + A_STG;

#pragma unroll
        for (int kk = 0; kk < 4; kk++) {
            uint32_t bfr[8];
#pragma unroll
            for (int p = 0; p < 2; p++) {
                uint32_t t[4];
                int r = wn + p * 16 + b_row;
                ldmatrix_x4(t, smem_u32(bs + r * LDS + kk * 16 + b_col));
                bfr[4 * p + 0] = t[0]; bfr[4 * p + 1] = t[1];
                bfr[4 * p + 2] = t[2]; bfr[4 * p + 3] = t[3];
            }
#pragma unroll
            for (int am = 0; am < 4; am++) {
                uint32_t af[4];
                int r = wm + am * 16 + a_row;
                ldmatrix_x4(af, smem_u32(as + r * LDS + kk * 16 + a_col));
#pragma unroll
                for (int an = 0; an < 4; an++)
                    mma16816(acc[am][an], af, &bfr[2 * an]);
            }
        }
    }

    // Epilogue
    const int tr = lane >> 2;
    const int tc = (lane & 3) * 2;
#pragma unroll
    for (int am = 0; am < 4; am++) {
#pragma unroll
        for (int an = 0; an < 4; an++) {
            int row0 = bm + wm + am * 16 + tr;
            int cl   = wn + an * 8 + tc;
            float* a = acc[am][an];
            float2 bb = *reinterpret_cast<const float2*>(&bias[cl]);
            if (EPI == 0) {
                *reinterpret_cast<__half2*>(&outH[(size_t)row0 * ldOut + cl]) =
                    __floats2half2_rn(a[0] + bb.x, a[1] + bb.y);
                *reinterpret_cast<__half2*>(&outH[(size_t)(row0 + 8) * ldOut + cl]) =
                    __floats2half2_rn(a[2] + bb.x, a[3] + bb.y);
            } else {
                size_t i0 = (size_t)row0 * ldOut + cl;
                size_t i1 = (size_t)(row0 + 8) * ldOut + cl;
                float2 r0 = *reinterpret_cast<const float2*>(&resid[i0]);
                float2 r1 = *reinterpret_cast<const float2*>(&resid[i1]);
                *reinterpret_cast<float2*>(&outF[i0]) =
                    make_float2(a[0] + bb.x + r0.x, a[1] + bb.y + r0.y);
                *reinterpret_cast<float2*>(&outF[i1]) =
                    make_float2(a[2] + bb.x + r1.x, a[3] + bb.y + r1.y);
            }
        }
    }
}

// ---------------------------------------------------------------------------
// Fused Q/K projections: one launch covers
//   gx in [0,8)  : Q     = img * Wq^T + bq -> g_Q
//   gx in [8,16) : K_img = img * Wk^T + bk -> g_K rows [0,B)
//   gx in [16,24): K_sig = sig * Wk^T + bk -> g_K rows [B,2B)
// ---------------------------------------------------------------------------
__global__ __launch_bounds__(256, 2) void k_qk(const float* __restrict__ bq,
                                               const float* __restrict__ bk) {
    const int gx = blockIdx.x;
    const int bm = blockIdx.y * BM;

    const __half* A;
    const __half* W;
    __half* out;
    const float* bias;

    if (gx < 8) {
        int col0 = gx * 128;
        A = g_AB;  W = g_Wq + (size_t)col0 * KDIM;
        out = g_Q + col0;  bias = bq + col0;
    } else if (gx < 16) {
        int col0 = (gx - 8) * 128;
        A = g_AB;  W = g_Wk + (size_t)col0 * KDIM;
        out = g_K + col0;  bias = bk + col0;
    } else {
        int col0 = (gx - 16) * 128;
        A = g_AB + (size_t)B_ * E_;  W = g_Wk + (size_t)col0 * KDIM;
        out = g_K + (size_t)B_ * E_ + col0;  bias = bk + col0;
    }
    gemm_core<0>(A, W, out, nullptr, bias, nullptr, bm, 1024);
}

// ---------------------------------------------------------------------------
// Fused scores + V-projection + attention combine (R7 fragment-mix + inlined
// softmax weights):
//   a0[r] = softmax over {q_r.k_img_r, q_r.k_sig_r} (head h), computed in the
//           prologue by 128 threads (two 128-dim dots each, uint4 loads).
//   ctx[:, h*128:(h+1)*128] = (a0*img + (1-a0)*sig) * Wv_h^T + bv_h
// A tiles (img & sig) both staged; mixing on fragments with per-row half2
// coefficients. 2-stage cp.async. smem: [2 x V_STGH] + a0s[128].
// ---------------------------------------------------------------------------
constexpr int V_STGH = 3 * A_STG;                    // img + sig + B
constexpr int V_SMEM = 2 * V_STGH * (int)sizeof(__half) + 512;  // 111104

__global__ __launch_bounds__(256, 2) void k_vgemm(const float* __restrict__ bv) {
    extern __shared__ __half smem[];
    float* a0s = reinterpret_cast<float*>(smem + 2 * V_STGH);

    const int h  = blockIdx.x;
    const int bm = blockIdx.y * BM;
    const int tid  = threadIdx.x;
    const int warp = tid >> 5;
    const int lane = tid & 31;
    const int wm   = (warp & 1) * 64;
    const int wn   = (warp >> 1) * 32;

    const __half* Aimg = g_AB;
    const __half* Asig = g_AB + (size_t)B_ * E_;
    const __half* W    = g_Wv + (size_t)h * 128 * KDIM;

    // ---- inlined scores: a0 for this CTA's 128 rows, head h ----
    if (tid < 128) {
        const int row = bm + tid;
        const uint4* q4 = reinterpret_cast<const uint4*>(g_Q + (size_t)row * E_ + h * D_);
        const uint4* ki4 = reinterpret_cast<const uint4*>(g_K + (size_t)row * E_ + h * D_);
        const uint4* ks4 = reinterpret_cast<const uint4*>(g_K + (size_t)(B_ + row) * E_ + h * D_);
        float d0 = 0.f, d1 = 0.f;
#pragma unroll
        for (int j = 0; j < 16; j++) {       // 16 x 8 halfs = 128 dims
            uint4 qv = q4[j], iv = ki4[j], sv = ks4[j];
            const __half2* qh = reinterpret_cast<const __half2*>(&qv);
            const __half2* ih = reinterpret_cast<const __half2*>(&iv);
            const __half2* sh = reinterpret_cast<const __half2*>(&sv);
#pragma unroll
            for (int t = 0; t < 4; t++) {
                float2 q = __half22float2(qh[t]);
                float2 a = __half22float2(ih[t]);
                float2 b = __half22float2(sh[t]);
                d0 += q.x * a.x + q.y * a.y;
                d1 += q.x * b.x + q.y * b.y;
            }
        }
        const float scale = 0.08838834764831845f;   // 1/sqrt(128)
        d0 *= scale; d1 *= scale;
        float m  = fmaxf(d0, d1);
        float e0 = __expf(d0 - m), e1 = __expf(d1 - m);
        a0s[tid] = e0 / (e0 + e1);
    }
    __syncthreads();

    float acc[4][4][4];
#pragma unroll
    for (int i = 0; i < 4; i++)
#pragma unroll
        for (int j = 0; j < 4; j++)
#pragma unroll
            for (int l = 0; l < 4; l++) acc[i][j][l] = 0.f;

    // per-row mixing coefficients (fragment rows g and g+8 per am)
    uint32_t c0[4][2], c1[4][2];
    {
        const int g = lane >> 2;
#pragma unroll
        for (int am = 0; am < 4; am++) {
            int r0 = wm + am * 16 + g;       // local row in [0,128)
            float ca = a0s[r0];
            float cb = a0s[r0 + 8];
            __half2 t;
            t = __float2half2_rn(ca);       c0[am][0] = *reinterpret_cast<uint32_t*>(&t);
            t = __float2half2_rn(1.f - ca); c1[am][0] = *reinterpret_cast<uint32_t*>(&t);
            t = __float2half2_rn(cb);       c0[am][1] = *reinterpret_cast<uint32_t*>(&t);
            t = __float2half2_rn(1.f - cb); c1[am][1] = *reinterpret_cast<uint32_t*>(&t);
        }
    }

    auto load_stage = [&](int stage, int kt) {
        const int k0 = kt * BK;
        __half* si = smem + stage * V_STGH;
        __half* ss = si + A_STG;
        __half* sb = si + 2 * A_STG;
#pragma unroll
        for (int i = 0; i < 12; i++) {
            int id = tid + i * 256;                  // 0..3071
            int row = (id & 1023) >> 3, seg = id & 7;
            if (id < 1024)
                cp16(smem_u32(si + row * LDS + seg * 8),
                     Aimg + (size_t)(bm + row) * KDIM + k0 + seg * 8);
            else if (id < 2048)
                cp16(smem_u32(ss + row * LDS + seg * 8),
                     Asig + (size_t)(bm + row) * KDIM + k0 + seg * 8);
            else
                cp16(smem_u32(sb + row * LDS + seg * 8),
                     W + (size_t)row * KDIM + k0 + seg * 8);
        }
    };

    load_stage(0, 0);
    cp_commit();

    const int a_row = (lane & 15);
    const int a_col = (lane >> 4) * 8;
    const int b_row = ((lane >> 4) << 3) + (lane & 7);
    const int b_col = ((lane >> 3) & 1) * 8;

    for (int kt = 0; kt < KT; kt++) {
        cp_wait<0>();
        __syncthreads();

        if (kt + 1 < KT) load_stage((kt + 1) & 1, kt + 1);
        cp_commit();

        const __half* ai = smem + (kt & 1) * V_STGH;
        const __half* as = ai + A_STG;
        const __half* bs = ai + 2 * A_STG;

#pragma unroll
        for (int kk = 0; kk < 4; kk++) {
            uint32_t bfr[8];
#pragma unroll
            for (int p = 0; p < 2; p++) {
                uint32_t t[4];
                int r = wn + p * 16 + b_row;
                ldmatrix_x4(t, smem_u32(bs + r * LDS + kk * 16 + b_col));
                bfr[4 * p + 0] = t[0]; bfr[4 * p + 1] = t[1];
                bfr[4 * p + 2] = t[2]; bfr[4 * p + 3] = t[3];
            }
#pragma unroll
            for (int am = 0; am < 4; am++) {
                uint32_t fi[4], fs[4], af[4];
                int r = wm + am * 16 + a_row;
                ldmatrix_x4(fi, smem_u32(ai + r * LDS + kk * 16 + a_col));
                ldmatrix_x4(fs, smem_u32(as + r * LDS + kk * 16 + a_col));
#pragma unroll
                for (int j = 0; j < 4; j++) {
                    const int half_sel = j & 1;      // regs 0,2 -> row g; 1,3 -> g+8
                    __half2 i2 = *reinterpret_cast<__half2*>(&fi[j]);
                    __half2 s2 = *reinterpret_cast<__half2*>(&fs[j]);
                    __half2 cc0 = *reinterpret_cast<__half2*>(&c0[am][half_sel]);
                    __half2 cc1 = *reinterpret_cast<__half2*>(&c1[am][half_sel]);
                    __half2 mx = __hfma2(i2, cc0, __hmul2(s2, cc1));
                    af[j] = *reinterpret_cast<uint32_t*>(&mx);
                }
#pragma unroll
                for (int an = 0; an < 4; an++)
                    mma16816(acc[am][an], af, &bfr[2 * an]);
            }
        }
    }

    // Epilogue -> g_ctx (half), bias = bv slice
    const int tr = lane >> 2;
    const int tc = (lane & 3) * 2;
    const float* bh = bv + h * 128;
    __half* outH = g_ctx + h * 128;
#pragma unroll
    for (int am = 0; am < 4; am++) {
#pragma unroll
        for (int an = 0; an < 4; an++) {
            int row0 = bm + wm + am * 16 + tr;
            int cl   = wn + an * 8 + tc;
            float* a = acc[am][an];
            float2 bb = *reinterpret_cast<const float2*>(&bh[cl]);
            *reinterpret_cast<__half2*>(&outH[(size_t)row0 * 1024 + cl]) =
                __floats2half2_rn(a[0] + bb.x, a[1] + bb.y);
            *reinterpret_cast<__half2*>(&outH[(size_t)(row0 + 8) * 1024 + cl]) =
                __floats2half2_rn(a[2] + bb.x, a[3] + bb.y);
        }
    }
}

// ---------------------------------------------------------------------------
// O-projection: fused = ctx * Wo^T + bo + img   (float out)
// ---------------------------------------------------------------------------
__global__ __launch_bounds__(256, 2) void k_ogemm(const float* __restrict__ bo,
                                                  const float* __restrict__ img) {
    const int col0 = blockIdx.x * 128;
    const int bm   = blockIdx.y * BM;
    gemm_core<1>(g_ctx, g_Wo + (size_t)col0 * KDIM, nullptr, g_fused + col0,
                 bo + col0, img + col0, bm, 1024);
}

// ---------------------------------------------------------------------------
// LayerNorm: one warp per row of 1024 floats.
// ---------------------------------------------------------------------------
__global__ void k_layernorm(const float* __restrict__ fused,
                            const float* __restrict__ gamma,
                            const float* __restrict__ beta,
                            float* __restrict__ out) {
    int row  = blockIdx.x * (blockDim.x >> 5) + (threadIdx.x >> 5);
    int lane = threadIdx.x & 31;
    if (row >= B_) return;

    const float4* r4 = reinterpret_cast<const float4*>(fused + (size_t)row * E_);
    float4 x[8];
    float s = 0.f, sq = 0.f;
#pragma unroll
    for (int j = 0; j < 8; j++) {
        x[j] = r4[lane + 32 * j];
        s  += x[j].x + x[j].y + x[j].z + x[j].w;
        sq += x[j].x * x[j].x + x[j].y * x[j].y + x[j].z * x[j].z + x[j].w * x[j].w;
    }
#pragma unroll
    for (int off = 16; off > 0; off >>= 1) {
        s  += __shfl_xor_sync(0xffffffffu, s,  off);
        sq += __shfl_xor_sync(0xffffffffu, sq, off);
    }
    float mean = s * (1.f / E_);
    float var  = sq * (1.f / E_) - mean * mean;
    float rstd = rsqrtf(var + 1e-5f);

    float4* o4 = reinterpret_cast<float4*>(out + (size_t)row * E_);
    const float4* g4 = reinterpret_cast<const float4*>(gamma);
    const float4* b4 = reinterpret_cast<const float4*>(beta);
#pragma unroll
    for (int j = 0; j < 8; j++) {
        int c = lane + 32 * j;
        float4 g = g4[c], bb = b4[c], r;
        r.x = (x[j].x - mean) * rstd * g.x + bb.x;
        r.y = (x[j].y - mean) * rstd * g.y + bb.y;
        r.z = (x[j].z - mean) * rstd * g.z + bb.z;
        r.w = (x[j].w - mean) * rstd * g.w + bb.w;
        o4[c] = r;
    }
}

// ---------------------------------------------------------------------------
// kernel_launch
// ---------------------------------------------------------------------------
extern "C" void kernel_launch(void* const* d_in, const int* in_sizes, int n_in,
                              void* d_out, int out_size) {
    const float* img   = (const float*)d_in[0];
    const float* sig   = (const float*)d_in[1];
    const float* wq    = (const float*)d_in[2];
    const float* wk    = (const float*)d_in[3];
    const float* wv    = (const float*)d_in[4];
    const float* bq    = (const float*)d_in[5];
    const float* bk    = (const float*)d_in[6];
    const float* bv    = (const float*)d_in[7];
    const float* wo    = (const float*)d_in[8];
    const float* bo    = (const float*)d_in[9];
    const float* gamma = (const float*)d_in[10];
    const float* beta  = (const float*)d_in[11];
    float* out = (float*)d_out;

    void* pFused;
    cudaGetSymbolAddress(&pFused, g_fused);

    cudaFuncSetAttribute(k_qk,    cudaFuncAttributeMaxDynamicSharedMemorySize, SMEM_BYTES);
    cudaFuncSetAttribute(k_vgemm, cudaFuncAttributeMaxDynamicSharedMemorySize, V_SMEM);
    cudaFuncSetAttribute(k_ogemm, cudaFuncAttributeMaxDynamicSharedMemorySize, SMEM_BYTES);

    // 1) conversions
    k_convert_all<<<CVT_TOT / 256, 256>>>(img, sig, wq, wk, wv, wo);

    // 2) Q + K_img + K_sig projections (3 GEMM units, one launch)
    k_qk<<<dim3(24, B_ / BM), 256, SMEM_BYTES>>>(bq, bk);

    // 3) fused scores + V-projection + combine -> ctx
    k_vgemm<<<dim3(H_, B_ / BM), 256, V_SMEM>>>(bv);

    // 4) fused = ctx * Wo^T + bo + img (float)
    k_ogemm<<<dim3(E_ / BN, B_ / BM), 256, SMEM_BYTES>>>(bo, img);

    // 5) LayerNorm -> out
    k_layernorm<<<B_ / 8, 256>>>((const float*)pFused, gamma, beta, out);
}

// round 11
// speedup vs baseline: 1.0431x; 1.0431x over previous
#include <cuda_runtime.h>
#include <cuda_fp16.h>
#include <cstdint>

// Problem constants
constexpr int B_ = 16384;
constexpr int E_ = 1024;
constexpr int H_ = 8;
constexpr int D_ = 128;

// ---------------------------------------------------------------------------
// Scratch (static device globals: allocation-free, graph-capture safe)
// ---------------------------------------------------------------------------
__device__ __half g_AB[2u * B_ * E_];           // [image; signal] fp16   (64 MB)
__device__ __half g_Wq[E_ * E_];
__device__ __half g_Wk[E_ * E_];
__device__ __half g_Wv[E_ * E_];
__device__ __half g_Wo[E_ * E_];
__device__ __half g_Q[(size_t)B_ * E_];         // q proj                 (32 MB)
__device__ __half g_K[(size_t)2 * B_ * E_];     // [k_img; k_sig]         (64 MB)
__device__ float  g_attw[(size_t)B_ * H_];      // a0 per (b,h)           (0.5MB)
__device__ __half g_ctx[(size_t)B_ * E_];       //                        (32 MB)
__device__ float  g_fused[(size_t)B_ * E_];     // attn_out + residual    (64 MB)

// ---------------------------------------------------------------------------
// PTX helpers (sm_80-class only: cp.async / ldmatrix / mma.sync)
// ---------------------------------------------------------------------------
__device__ __forceinline__ uint32_t smem_u32(const void* p) {
    return (uint32_t)__cvta_generic_to_shared(p);
}
__device__ __forceinline__ void cp16(uint32_t s, const void* g) {
    asm volatile("cp.async.cg.shared.global [%0], [%1], 16;\n" :: "r"(s), "l"(g));
}
__device__ __forceinline__ void cp_commit() {
    asm volatile("cp.async.commit_group;\n");
}
template <int N>
__device__ __forceinline__ void cp_wait() {
    asm volatile("cp.async.wait_group %0;\n" :: "n"(N));
}
__device__ __forceinline__ void ldmatrix_x4(uint32_t* r, uint32_t addr) {
    asm volatile("ldmatrix.sync.aligned.m8n8.x4.shared.b16 {%0,%1,%2,%3}, [%4];\n"
                 : "=r"(r[0]), "=r"(r[1]), "=r"(r[2]), "=r"(r[3]) : "r"(addr));
}
__device__ __forceinline__ void mma16816(float* c, const uint32_t* a, const uint32_t* b) {
    asm volatile("mma.sync.aligned.m16n8k16.row.col.f32.f16.f16.f32 "
                 "{%0,%1,%2,%3}, {%4,%5,%6,%7}, {%8,%9}, {%0,%1,%2,%3};\n"
                 : "+f"(c[0]), "+f"(c[1]), "+f"(c[2]), "+f"(c[3])
                 : "r"(a[0]), "r"(a[1]), "r"(a[2]), "r"(a[3]), "r"(b[0]), "r"(b[1]));
}

// ---------------------------------------------------------------------------
// Single conversion kernel (inputs fp32->fp16, weights fp32->fp16)
// ---------------------------------------------------------------------------
constexpr int IN4 = (2 * B_ * E_) / 4;        // 8388608
constexpr int W4  = (4 * E_ * E_) / 4;        // 1048576
constexpr int CVT_TOT = IN4 + W4;             // divisible by 256

__global__ void k_convert_all(const float* __restrict__ img, const float* __restrict__ sig,
                              const float* __restrict__ wq, const float* __restrict__ wk,
                              const float* __restrict__ wv, const float* __restrict__ wo) {
    int i = blockIdx.x * blockDim.x + threadIdx.x;
    if (i < IN4) {
        const int n4 = (B_ * E_) / 4;
        float4 v = (i < n4) ? reinterpret_cast<const float4*>(img)[i]
                            : reinterpret_cast<const float4*>(sig)[i - n4];
        __half* dst = g_AB + (size_t)4 * i;
        *reinterpret_cast<__half2*>(dst)     = __floats2half2_rn(v.x, v.y);
        *reinterpret_cast<__half2*>(dst + 2) = __floats2half2_rn(v.z, v.w);
    } else {
        int j = i - IN4;
        const int per = (E_ * E_) / 4;
        int m = j / per;
        int t = j - m * per;
        const float* src;
        __half* dst;
        if (m == 0)      { src = wq; dst = g_Wq; }
        else if (m == 1) { src = wk; dst = g_Wk; }
        else if (m == 2) { src = wv; dst = g_Wv; }
        else             { src = wo; dst = g_Wo; }
        float4 v = reinterpret_cast<const float4*>(src)[t];
        dst += (size_t)4 * t;
        *reinterpret_cast<__half2*>(dst)     = __floats2half2_rn(v.x, v.y);
        *reinterpret_cast<__half2*>(dst + 2) = __floats2half2_rn(v.z, v.w);
    }
}

// ---------------------------------------------------------------------------
// Shared GEMM core: C[*, cl] = A[M,1024] * W[128 rows,1024]^T (NT), fp16->fp32.
// CTA tile 128x128x64, 3-stage cp.async, 8 warps (2M x 4N), warp 64x32.
// EPI=0: half out = acc + bias[cl];  EPI=1: float out = acc + bias + resid
// ---------------------------------------------------------------------------
constexpr int BM = 128, BN = 128, BK = 64, STAGES = 3;
constexpr int KDIM = 1024, KT = KDIM / BK;           // 16
constexpr int LDS = BK + 8;                          // 72 halfs / 144B row
constexpr int A_STG = BM * LDS;                      // 9216 halfs
constexpr int STG   = 2 * A_STG;
constexpr int SMEM_BYTES = STAGES * STG * (int)sizeof(__half);   // 110592

template <int EPI>
__device__ __forceinline__ void gemm_core(
    const __half* __restrict__ A,
    const __half* __restrict__ W,
    __half* __restrict__ outH,
    float* __restrict__ outF,
    const float* __restrict__ bias,
    const float* __restrict__ resid,
    int bm, int ldOut)
{
    extern __shared__ __half smem[];

    const int tid  = threadIdx.x;
    const int warp = tid >> 5;
    const int lane = tid & 31;
    const int wm   = (warp & 1) * 64;
    const int wn   = (warp >> 1) * 32;

    float acc[4][4][4];
#pragma unroll
    for (int i = 0; i < 4; i++)
#pragma unroll
        for (int j = 0; j < 4; j++)
#pragma unroll
            for (int l = 0; l < 4; l++) acc[i][j][l] = 0.f;

    auto load_stage = [&](int stage, int kt) {
        const int k0 = kt * BK;
        __half* sa = smem + stage * STG;
        __half* sb = sa + A_STG;
#pragma unroll
        for (int i = 0; i < 8; i++) {
            int id = tid + i * 256;
            if (id < 1024) {
                int row = id >> 3, seg = id & 7;
                cp16(smem_u32(sa + row * LDS + seg * 8),
                     A + (size_t)(bm + row) * KDIM + k0 + seg * 8);
            } else {
                id -= 1024;
                int row = id >> 3, seg = id & 7;
                cp16(smem_u32(sb + row * LDS + seg * 8),
                     W + (size_t)row * KDIM + k0 + seg * 8);
            }
        }
    };

#pragma unroll
    for (int s = 0; s < STAGES - 1; s++) { load_stage(s, s); cp_commit(); }

    const int a_row = (lane & 15);
    const int a_col = (lane >> 4) * 8;
    const int b_row = ((lane >> 4) << 3) + (lane & 7);
    const int b_col = ((lane >> 3) & 1) * 8;

    for (int kt = 0; kt < KT; kt++) {
        cp_wait<STAGES - 2>();
        __syncthreads();

        if (kt + STAGES - 1 < KT) load_stage((kt + STAGES - 1) % STAGES, kt + STAGES - 1);
        cp_commit();

        const __half* as = smem + (kt % STAGES) * STG;
        const __half* bs = as + A_STG;

#pragma unroll
        for (int kk = 0; kk < 4; kk++) {
            uint32_t bfr[8];
#pragma unroll
            for (int p = 0; p < 2; p++) {
                uint32_t t[4];
                int r = wn + p * 16 + b_row;
                ldmatrix_x4(t, smem_u32(bs + r * LDS + kk * 16 + b_col));
                bfr[4 * p + 0] = t[0]; bfr[4 * p + 1] = t[1];
                bfr[4 * p + 2] = t[2]; bfr[4 * p + 3] = t[3];
            }
#pragma unroll
            for (int am = 0; am < 4; am++) {
                uint32_t af[4];
                int r = wm + am * 16 + a_row;
                ldmatrix_x4(af, smem_u32(as + r * LDS + kk * 16 + a_col));
#pragma unroll
                for (int an = 0; an < 4; an++)
                    mma16816(acc[am][an], af, &bfr[2 * an]);
            }
        }
    }

    // Epilogue
    const int tr = lane >> 2;
    const int tc = (lane & 3) * 2;
#pragma unroll
    for (int am = 0; am < 4; am++) {
#pragma unroll
        for (int an = 0; an < 4; an++) {
            int row0 = bm + wm + am * 16 + tr;
            int cl   = wn + an * 8 + tc;
            float* a = acc[am][an];
            float2 bb = *reinterpret_cast<const float2*>(&bias[cl]);
            if (EPI == 0) {
                *reinterpret_cast<__half2*>(&outH[(size_t)row0 * ldOut + cl]) =
                    __floats2half2_rn(a[0] + bb.x, a[1] + bb.y);
                *reinterpret_cast<__half2*>(&outH[(size_t)(row0 + 8) * ldOut + cl]) =
                    __floats2half2_rn(a[2] + bb.x, a[3] + bb.y);
            } else {
                size_t i0 = (size_t)row0 * ldOut + cl;
                size_t i1 = (size_t)(row0 + 8) * ldOut + cl;
                float2 r0 = *reinterpret_cast<const float2*>(&resid[i0]);
                float2 r1 = *reinterpret_cast<const float2*>(&resid[i1]);
                *reinterpret_cast<float2*>(&outF[i0]) =
                    make_float2(a[0] + bb.x + r0.x, a[1] + bb.y + r0.y);
                *reinterpret_cast<float2*>(&outF[i1]) =
                    make_float2(a[2] + bb.x + r1.x, a[3] + bb.y + r1.y);
            }
        }
    }
}

// ---------------------------------------------------------------------------
// Fused Q/K projections: one launch covers
//   gx in [0,8)  : Q     = img * Wq^T + bq -> g_Q
//   gx in [8,16) : K_img = img * Wk^T + bk -> g_K rows [0,B)
//   gx in [16,24): K_sig = sig * Wk^T + bk -> g_K rows [B,2B)
// ---------------------------------------------------------------------------
__global__ __launch_bounds__(256, 2) void k_qk(const float* __restrict__ bq,
                                               const float* __restrict__ bk) {
    const int gx = blockIdx.x;
    const int bm = blockIdx.y * BM;

    const __half* A;
    const __half* W;
    __half* out;
    const float* bias;

    if (gx < 8) {
        int col0 = gx * 128;
        A = g_AB;  W = g_Wq + (size_t)col0 * KDIM;
        out = g_Q + col0;  bias = bq + col0;
    } else if (gx < 16) {
        int col0 = (gx - 8) * 128;
        A = g_AB;  W = g_Wk + (size_t)col0 * KDIM;
        out = g_K + col0;  bias = bk + col0;
    } else {
        int col0 = (gx - 16) * 128;
        A = g_AB + (size_t)B_ * E_;  W = g_Wk + (size_t)col0 * KDIM;
        out = g_K + (size_t)B_ * E_ + col0;  bias = bk + col0;
    }
    gemm_core<0>(A, W, out, nullptr, bias, nullptr, bm, 1024);
}

// ---------------------------------------------------------------------------
// Scores: one warp per (b,h); 2-way softmax -> a0 weight only.
// ---------------------------------------------------------------------------
__global__ void k_scores(const __half* __restrict__ Q, const __half* __restrict__ K) {
    int gw   = blockIdx.x * (blockDim.x >> 5) + (threadIdx.x >> 5);
    int lane = threadIdx.x & 31;
    int b = gw >> 3;
    int h = gw & 7;
    if (b >= B_) return;

    const __half2* q2  = reinterpret_cast<const __half2*>(Q + (size_t)b * E_ + h * D_) + lane * 2;
    const __half2* ki2 = reinterpret_cast<const __half2*>(K + (size_t)b * E_ + h * D_) + lane * 2;
    const __half2* ks2 = reinterpret_cast<const __half2*>(K + (size_t)(B_ + b) * E_ + h * D_) + lane * 2;

    float2 qa = __half22float2(q2[0]),  qb = __half22float2(q2[1]);
    float2 ka = __half22float2(ki2[0]), kb = __half22float2(ki2[1]);
    float2 sa = __half22float2(ks2[0]), sb = __half22float2(ks2[1]);

    float d0 = qa.x * ka.x + qa.y * ka.y + qb.x * kb.x + qb.y * kb.y;
    float d1 = qa.x * sa.x + qa.y * sa.y + qb.x * sb.x + qb.y * sb.y;
#pragma unroll
    for (int off = 16; off > 0; off >>= 1) {
        d0 += __shfl_xor_sync(0xffffffffu, d0, off);
        d1 += __shfl_xor_sync(0xffffffffu, d1, off);
    }
    const float scale = 0.08838834764831845f;   // 1/sqrt(128)
    d0 *= scale; d1 *= scale;
    float m  = fmaxf(d0, d1);
    float e0 = __expf(d0 - m), e1 = __expf(d1 - m);
    float a0 = e0 / (e0 + e1);
    if (lane == 0) g_attw[(size_t)b * H_ + h] = a0;
}

// ---------------------------------------------------------------------------
// Fused V-projection + attention combine (R7 fragment-mix — best known):
//   ctx[:, h*128:(h+1)*128] = (a0_h*img + (1-a0_h)*sig) * Wv_h^T + bv_h
// A tiles (img & sig) both staged; mixing done on fragments with per-row
// half2 coefficients (fma pipe, overlaps tensor). 2-stage cp.async.
// ---------------------------------------------------------------------------
constexpr int V_STGH = 3 * A_STG;                    // img + sig + B
constexpr int V_SMEM = 2 * V_STGH * (int)sizeof(__half);  // 110592

__global__ __launch_bounds__(256, 2) void k_vgemm(const float* __restrict__ bv) {
    extern __shared__ __half smem[];

    const int h  = blockIdx.x;
    const int bm = blockIdx.y * BM;
    const int tid  = threadIdx.x;
    const int warp = tid >> 5;
    const int lane = tid & 31;
    const int wm   = (warp & 1) * 64;
    const int wn   = (warp >> 1) * 32;

    const __half* Aimg = g_AB;
    const __half* Asig = g_AB + (size_t)B_ * E_;
    const __half* W    = g_Wv + (size_t)h * 128 * KDIM;

    float acc[4][4][4];
#pragma unroll
    for (int i = 0; i < 4; i++)
#pragma unroll
        for (int j = 0; j < 4; j++)
#pragma unroll
            for (int l = 0; l < 4; l++) acc[i][j][l] = 0.f;

    // per-row mixing coefficients (fragment rows g and g+8 per am)
    uint32_t c0[4][2], c1[4][2];
    {
        const int g = lane >> 2;
#pragma unroll
        for (int am = 0; am < 4; am++) {
            int r0 = bm + wm + am * 16 + g;
            float ca = g_attw[(size_t)r0 * H_ + h];
            float cb = g_attw[(size_t)(r0 + 8) * H_ + h];
            __half2 t;
            t = __float2half2_rn(ca);       c0[am][0] = *reinterpret_cast<uint32_t*>(&t);
            t = __float2half2_rn(1.f - ca); c1[am][0] = *reinterpret_cast<uint32_t*>(&t);
            t = __float2half2_rn(cb);       c0[am][1] = *reinterpret_cast<uint32_t*>(&t);
            t = __float2half2_rn(1.f - cb); c1[am][1] = *reinterpret_cast<uint32_t*>(&t);
        }
    }

    auto load_stage = [&](int stage, int kt) {
        const int k0 = kt * BK;
        __half* si = smem + stage * V_STGH;
        __half* ss = si + A_STG;
        __half* sb = si + 2 * A_STG;
#pragma unroll
        for (int i = 0; i < 12; i++) {
            int id = tid + i * 256;                  // 0..3071
            int row = (id & 1023) >> 3, seg = id & 7;
            if (id < 1024)
                cp16(smem_u32(si + row * LDS + seg * 8),
                     Aimg + (size_t)(bm + row) * KDIM + k0 + seg * 8);
            else if (id < 2048)
                cp16(smem_u32(ss + row * LDS + seg * 8),
                     Asig + (size_t)(bm + row) * KDIM + k0 + seg * 8);
            else
                cp16(smem_u32(sb + row * LDS + seg * 8),
                     W + (size_t)row * KDIM + k0 + seg * 8);
        }
    };

    load_stage(0, 0);
    cp_commit();

    const int a_row = (lane & 15);
    const int a_col = (lane >> 4) * 8;
    const int b_row = ((lane >> 4) << 3) + (lane & 7);
    const int b_col = ((lane >> 3) & 1) * 8;

    for (int kt = 0; kt < KT; kt++) {
        cp_wait<0>();
        __syncthreads();

        if (kt + 1 < KT) load_stage((kt + 1) & 1, kt + 1);
        cp_commit();

        const __half* ai = smem + (kt & 1) * V_STGH;
        const __half* as = ai + A_STG;
        const __half* bs = ai + 2 * A_STG;

#pragma unroll
        for (int kk = 0; kk < 4; kk++) {
            uint32_t bfr[8];
#pragma unroll
            for (int p = 0; p < 2; p++) {
                uint32_t t[4];
                int r = wn + p * 16 + b_row;
                ldmatrix_x4(t, smem_u32(bs + r * LDS + kk * 16 + b_col));
                bfr[4 * p + 0] = t[0]; bfr[4 * p + 1] = t[1];
                bfr[4 * p + 2] = t[2]; bfr[4 * p + 3] = t[3];
            }
#pragma unroll
            for (int am = 0; am < 4; am++) {
                uint32_t fi[4], fs[4], af[4];
                int r = wm + am * 16 + a_row;
                ldmatrix_x4(fi, smem_u32(ai + r * LDS + kk * 16 + a_col));
                ldmatrix_x4(fs, smem_u32(as + r * LDS + kk * 16 + a_col));
#pragma unroll
                for (int j = 0; j < 4; j++) {
                    const int half_sel = j & 1;      // regs 0,2 -> row g; 1,3 -> g+8
                    __half2 i2 = *reinterpret_cast<__half2*>(&fi[j]);
                    __half2 s2 = *reinterpret_cast<__half2*>(&fs[j]);
                    __half2 cc0 = *reinterpret_cast<__half2*>(&c0[am][half_sel]);
                    __half2 cc1 = *reinterpret_cast<__half2*>(&c1[am][half_sel]);
                    __half2 mx = __hfma2(i2, cc0, __hmul2(s2, cc1));
                    af[j] = *reinterpret_cast<uint32_t*>(&mx);
                }
#pragma unroll
                for (int an = 0; an < 4; an++)
                    mma16816(acc[am][an], af, &bfr[2 * an]);
            }
        }
    }

    // Epilogue -> g_ctx (half), bias = bv slice
    const int tr = lane >> 2;
    const int tc = (lane & 3) * 2;
    const float* bh = bv + h * 128;
    __half* outH = g_ctx + h * 128;
#pragma unroll
    for (int am = 0; am < 4; am++) {
#pragma unroll
        for (int an = 0; an < 4; an++) {
            int row0 = bm + wm + am * 16 + tr;
            int cl   = wn + an * 8 + tc;
            float* a = acc[am][an];
            float2 bb = *reinterpret_cast<const float2*>(&bh[cl]);
            *reinterpret_cast<__half2*>(&outH[(size_t)row0 * 1024 + cl]) =
                __floats2half2_rn(a[0] + bb.x, a[1] + bb.y);
            *reinterpret_cast<__half2*>(&outH[(size_t)(row0 + 8) * 1024 + cl]) =
                __floats2half2_rn(a[2] + bb.x, a[3] + bb.y);
        }
    }
}

// ---------------------------------------------------------------------------
// O-projection: fused = ctx * Wo^T + bo + img   (float out)
// ---------------------------------------------------------------------------
__global__ __launch_bounds__(256, 2) void k_ogemm(const float* __restrict__ bo,
                                                  const float* __restrict__ img) {
    const int col0 = blockIdx.x * 128;
    const int bm   = blockIdx.y * BM;
    gemm_core<1>(g_ctx, g_Wo + (size_t)col0 * KDIM, nullptr, g_fused + col0,
                 bo + col0, img + col0, bm, 1024);
}

// ---------------------------------------------------------------------------
// LayerNorm: one warp per row of 1024 floats.
// ---------------------------------------------------------------------------
__global__ void k_layernorm(const float* __restrict__ fused,
                            const float* __restrict__ gamma,
                            const float* __restrict__ beta,
                            float* __restrict__ out) {
    int row  = blockIdx.x * (blockDim.x >> 5) + (threadIdx.x >> 5);
    int lane = threadIdx.x & 31;
    if (row >= B_) return;

    const float4* r4 = reinterpret_cast<const float4*>(fused + (size_t)row * E_);
    float4 x[8];
    float s = 0.f, sq = 0.f;
#pragma unroll
    for (int j = 0; j < 8; j++) {
        x[j] = r4[lane + 32 * j];
        s  += x[j].x + x[j].y + x[j].z + x[j].w;
        sq += x[j].x * x[j].x + x[j].y * x[j].y + x[j].z * x[j].z + x[j].w * x[j].w;
    }
#pragma unroll
    for (int off = 16; off > 0; off >>= 1) {
        s  += __shfl_xor_sync(0xffffffffu, s,  off);
        sq += __shfl_xor_sync(0xffffffffu, sq, off);
    }
    float mean = s * (1.f / E_);
    float var  = sq * (1.f / E_) - mean * mean;
    float rstd = rsqrtf(var + 1e-5f);

    float4* o4 = reinterpret_cast<float4*>(out + (size_t)row * E_);
    const float4* g4 = reinterpret_cast<const float4*>(gamma);
    const float4* b4 = reinterpret_cast<const float4*>(beta);
#pragma unroll
    for (int j = 0; j < 8; j++) {
        int c = lane + 32 * j;
        float4 g = g4[c], bb = b4[c], r;
        r.x = (x[j].x - mean) * rstd * g.x + bb.x;
        r.y = (x[j].y - mean) * rstd * g.y + bb.y;
        r.z = (x[j].z - mean) * rstd * g.z + bb.z;
        r.w = (x[j].w - mean) * rstd * g.w + bb.w;
        o4[c] = r;
    }
}

// ---------------------------------------------------------------------------
// kernel_launch
// ---------------------------------------------------------------------------
extern "C" void kernel_launch(void* const* d_in, const int* in_sizes, int n_in,
                              void* d_out, int out_size) {
    const float* img   = (const float*)d_in[0];
    const float* sig   = (const float*)d_in[1];
    const float* wq    = (const float*)d_in[2];
    const float* wk    = (const float*)d_in[3];
    const float* wv    = (const float*)d_in[4];
    const float* bq    = (const float*)d_in[5];
    const float* bk    = (const float*)d_in[6];
    const float* bv    = (const float*)d_in[7];
    const float* wo    = (const float*)d_in[8];
    const float* bo    = (const float*)d_in[9];
    const float* gamma = (const float*)d_in[10];
    const float* beta  = (const float*)d_in[11];
    float* out = (float*)d_out;

    void *pQ, *pK, *pFused;
    cudaGetSymbolAddress(&pQ,     g_Q);
    cudaGetSymbolAddress(&pK,     g_K);
    cudaGetSymbolAddress(&pFused, g_fused);

    cudaFuncSetAttribute(k_qk,    cudaFuncAttributeMaxDynamicSharedMemorySize, SMEM_BYTES);
    cudaFuncSetAttribute(k_vgemm, cudaFuncAttributeMaxDynamicSharedMemorySize, V_SMEM);
    cudaFuncSetAttribute(k_ogemm, cudaFuncAttributeMaxDynamicSharedMemorySize, SMEM_BYTES);

    // 1) conversions
    k_convert_all<<<CVT_TOT / 256, 256>>>(img, sig, wq, wk, wv, wo);

    // 2) Q + K_img + K_sig projections (3 GEMM units, one launch)
    k_qk<<<dim3(24, B_ / BM), 256, SMEM_BYTES>>>(bq, bk);

    // 3) attention weights a0[b,h]
    k_scores<<<(B_ * H_) / 8, 256>>>((const __half*)pQ, (const __half*)pK);

    // 4) fused V-projection + combine -> ctx (fragment-mix, best known)
    k_vgemm<<<dim3(H_, B_ / BM), 256, V_SMEM>>>(bv);

    // 5) fused = ctx * Wo^T + bo + img (float)
    k_ogemm<<<dim3(E_ / BN, B_ / BM), 256, SMEM_BYTES>>>(bo, img);

    // 6) LayerNorm -> out
    k_layernorm<<<B_ / 8, 256>>>((const float*)pFused, gamma, beta, out);
}

// round 12
// speedup vs baseline: 1.0453x; 1.0021x over previous
#include <cuda_runtime.h>
#include <cuda_fp16.h>
#include <cstdint>

// Problem constants
constexpr int B_ = 16384;
constexpr int E_ = 1024;
constexpr int H_ = 8;
constexpr int D_ = 128;

// ---------------------------------------------------------------------------
// Scratch (static device globals: allocation-free, graph-capture safe)
// ---------------------------------------------------------------------------
__device__ __half g_AB[2u * B_ * E_];           // [image; signal] fp16   (64 MB)
__device__ __half g_Wq[E_ * E_];
__device__ __half g_Wk[E_ * E_];
__device__ __half g_Wv[E_ * E_];
__device__ __half g_Wo[E_ * E_];
__device__ __half g_Q[(size_t)B_ * E_];         // q proj                 (32 MB)
__device__ __half g_K[(size_t)2 * B_ * E_];     // [k_img; k_sig]         (64 MB)
__device__ float  g_attw[(size_t)B_ * H_];      // a0 per (b,h)           (0.5MB)
__device__ __half g_ctx[(size_t)B_ * E_];       //                        (32 MB)
__device__ __half g_fused[(size_t)B_ * E_];     // attn_out + residual    (32 MB, fp16)

// ---------------------------------------------------------------------------
// PTX helpers (sm_80-class only: cp.async / ldmatrix / mma.sync)
// ---------------------------------------------------------------------------
__device__ __forceinline__ uint32_t smem_u32(const void* p) {
    return (uint32_t)__cvta_generic_to_shared(p);
}
__device__ __forceinline__ void cp16(uint32_t s, const void* g) {
    asm volatile("cp.async.cg.shared.global [%0], [%1], 16;\n" :: "r"(s), "l"(g));
}
__device__ __forceinline__ void cp_commit() {
    asm volatile("cp.async.commit_group;\n");
}
template <int N>
__device__ __forceinline__ void cp_wait() {
    asm volatile("cp.async.wait_group %0;\n" :: "n"(N));
}
__device__ __forceinline__ void ldmatrix_x4(uint32_t* r, uint32_t addr) {
    asm volatile("ldmatrix.sync.aligned.m8n8.x4.shared.b16 {%0,%1,%2,%3}, [%4];\n"
                 : "=r"(r[0]), "=r"(r[1]), "=r"(r[2]), "=r"(r[3]) : "r"(addr));
}
__device__ __forceinline__ void mma16816(float* c, const uint32_t* a, const uint32_t* b) {
    asm volatile("mma.sync.aligned.m16n8k16.row.col.f32.f16.f16.f32 "
                 "{%0,%1,%2,%3}, {%4,%5,%6,%7}, {%8,%9}, {%0,%1,%2,%3};\n"
                 : "+f"(c[0]), "+f"(c[1]), "+f"(c[2]), "+f"(c[3])
                 : "r"(a[0]), "r"(a[1]), "r"(a[2]), "r"(a[3]), "r"(b[0]), "r"(b[1]));
}

// ---------------------------------------------------------------------------
// Single conversion kernel (inputs fp32->fp16, weights fp32->fp16)
// ---------------------------------------------------------------------------
constexpr int IN4 = (2 * B_ * E_) / 4;        // 8388608
constexpr int W4  = (4 * E_ * E_) / 4;        // 1048576
constexpr int CVT_TOT = IN4 + W4;             // divisible by 256

__global__ void k_convert_all(const float* __restrict__ img, const float* __restrict__ sig,
                              const float* __restrict__ wq, const float* __restrict__ wk,
                              const float* __restrict__ wv, const float* __restrict__ wo) {
    int i = blockIdx.x * blockDim.x + threadIdx.x;
    if (i < IN4) {
        const int n4 = (B_ * E_) / 4;
        float4 v = (i < n4) ? reinterpret_cast<const float4*>(img)[i]
                            : reinterpret_cast<const float4*>(sig)[i - n4];
        __half* dst = g_AB + (size_t)4 * i;
        *reinterpret_cast<__half2*>(dst)     = __floats2half2_rn(v.x, v.y);
        *reinterpret_cast<__half2*>(dst + 2) = __floats2half2_rn(v.z, v.w);
    } else {
        int j = i - IN4;
        const int per = (E_ * E_) / 4;
        int m = j / per;
        int t = j - m * per;
        const float* src;
        __half* dst;
        if (m == 0)      { src = wq; dst = g_Wq; }
        else if (m == 1) { src = wk; dst = g_Wk; }
        else if (m == 2) { src = wv; dst = g_Wv; }
        else             { src = wo; dst = g_Wo; }
        float4 v = reinterpret_cast<const float4*>(src)[t];
        dst += (size_t)4 * t;
        *reinterpret_cast<__half2*>(dst)     = __floats2half2_rn(v.x, v.y);
        *reinterpret_cast<__half2*>(dst + 2) = __floats2half2_rn(v.z, v.w);
    }
}

// ---------------------------------------------------------------------------
// Shared GEMM core: C[*, cl] = A[M,1024] * W[128 rows,1024]^T (NT), fp16->fp32.
// CTA tile 128x128x64, 3-stage cp.async, 8 warps (2M x 4N), warp 64x32.
// EPI=0: half out = acc + bias[cl]
// EPI=1: half out = acc + bias[cl] + residH[row*ldOut+cl]   (fp16 residual)
// ---------------------------------------------------------------------------
constexpr int BM = 128, BN = 128, BK = 64, STAGES = 3;
constexpr int KDIM = 1024, KT = KDIM / BK;           // 16
constexpr int LDS = BK + 8;                          // 72 halfs / 144B row
constexpr int A_STG = BM * LDS;                      // 9216 halfs
constexpr int STG   = 2 * A_STG;
constexpr int SMEM_BYTES = STAGES * STG * (int)sizeof(__half);   // 110592

template <int EPI>
__device__ __forceinline__ void gemm_core(
    const __half* __restrict__ A,
    const __half* __restrict__ W,
    __half* __restrict__ outH,
    const float* __restrict__ bias,
    const __half* __restrict__ residH,
    int bm, int ldOut)
{
    extern __shared__ __half smem[];

    const int tid  = threadIdx.x;
    const int warp = tid >> 5;
    const int lane = tid & 31;
    const int wm   = (warp & 1) * 64;
    const int wn   = (warp >> 1) * 32;

    float acc[4][4][4];
#pragma unroll
    for (int i = 0; i < 4; i++)
#pragma unroll
        for (int j = 0; j < 4; j++)
#pragma unroll
            for (int l = 0; l < 4; l++) acc[i][j][l] = 0.f;

    auto load_stage = [&](int stage, int kt) {
        const int k0 = kt * BK;
        __half* sa = smem + stage * STG;
        __half* sb = sa + A_STG;
#pragma unroll
        for (int i = 0; i < 8; i++) {
            int id = tid + i * 256;
            if (id < 1024) {
                int row = id >> 3, seg = id & 7;
                cp16(smem_u32(sa + row * LDS + seg * 8),
                     A + (size_t)(bm + row) * KDIM + k0 + seg * 8);
            } else {
                id -= 1024;
                int row = id >> 3, seg = id & 7;
                cp16(smem_u32(sb + row * LDS + seg * 8),
                     W + (size_t)row * KDIM + k0 + seg * 8);
            }
        }
    };

#pragma unroll
    for (int s = 0; s < STAGES - 1; s++) { load_stage(s, s); cp_commit(); }

    const int a_row = (lane & 15);
    const int a_col = (lane >> 4) * 8;
    const int b_row = ((lane >> 4) << 3) + (lane & 7);
    const int b_col = ((lane >> 3) & 1) * 8;

    for (int kt = 0; kt < KT; kt++) {
        cp_wait<STAGES - 2>();
        __syncthreads();

        if (kt + STAGES - 1 < KT) load_stage((kt + STAGES - 1) % STAGES, kt + STAGES - 1);
        cp_commit();

        const __half* as = smem + (kt % STAGES) * STG;
        const __half* bs = as + A_STG;

#pragma unroll
        for (int kk = 0; kk < 4; kk++) {
            uint32_t bfr[8];
#pragma unroll
            for (int p = 0; p < 2; p++) {
                uint32_t t[4];
                int r = wn + p * 16 + b_row;
                ldmatrix_x4(t, smem_u32(bs + r * LDS + kk * 16 + b_col));
                bfr[4 * p + 0] = t[0]; bfr[4 * p + 1] = t[1];
                bfr[4 * p + 2] = t[2]; bfr[4 * p + 3] = t[3];
            }
#pragma unroll
            for (int am = 0; am < 4; am++) {
                uint32_t af[4];
                int r = wm + am * 16 + a_row;
                ldmatrix_x4(af, smem_u32(as + r * LDS + kk * 16 + a_col));
#pragma unroll
                for (int an = 0; an < 4; an++)
                    mma16816(acc[am][an], af, &bfr[2 * an]);
            }
        }
    }

    // Epilogue
    const int tr = lane >> 2;
    const int tc = (lane & 3) * 2;
#pragma unroll
    for (int am = 0; am < 4; am++) {
#pragma unroll
        for (int an = 0; an < 4; an++) {
            int row0 = bm + wm + am * 16 + tr;
            int cl   = wn + an * 8 + tc;
            float* a = acc[am][an];
            float2 bb = *reinterpret_cast<const float2*>(&bias[cl]);
            size_t i0 = (size_t)row0 * ldOut + cl;
            size_t i1 = (size_t)(row0 + 8) * ldOut + cl;
            if (EPI == 0) {
                *reinterpret_cast<__half2*>(&outH[i0]) =
                    __floats2half2_rn(a[0] + bb.x, a[1] + bb.y);
                *reinterpret_cast<__half2*>(&outH[i1]) =
                    __floats2half2_rn(a[2] + bb.x, a[3] + bb.y);
            } else {
                float2 r0 = __half22float2(*reinterpret_cast<const __half2*>(&residH[i0]));
                float2 r1 = __half22float2(*reinterpret_cast<const __half2*>(&residH[i1]));
                *reinterpret_cast<__half2*>(&outH[i0]) =
                    __floats2half2_rn(a[0] + bb.x + r0.x, a[1] + bb.y + r0.y);
                *reinterpret_cast<__half2*>(&outH[i1]) =
                    __floats2half2_rn(a[2] + bb.x + r1.x, a[3] + bb.y + r1.y);
            }
        }
    }
}

// ---------------------------------------------------------------------------
// Fused Q/K projections: one launch covers
//   gx in [0,8)  : Q     = img * Wq^T + bq -> g_Q
//   gx in [8,16) : K_img = img * Wk^T + bk -> g_K rows [0,B)
//   gx in [16,24): K_sig = sig * Wk^T + bk -> g_K rows [B,2B)
// ---------------------------------------------------------------------------
__global__ __launch_bounds__(256, 2) void k_qk(const float* __restrict__ bq,
                                               const float* __restrict__ bk) {
    const int gx = blockIdx.x;
    const int bm = blockIdx.y * BM;

    const __half* A;
    const __half* W;
    __half* out;
    const float* bias;

    if (gx < 8) {
        int col0 = gx * 128;
        A = g_AB;  W = g_Wq + (size_t)col0 * KDIM;
        out = g_Q + col0;  bias = bq + col0;
    } else if (gx < 16) {
        int col0 = (gx - 8) * 128;
        A = g_AB;  W = g_Wk + (size_t)col0 * KDIM;
        out = g_K + col0;  bias = bk + col0;
    } else {
        int col0 = (gx - 16) * 128;
        A = g_AB + (size_t)B_ * E_;  W = g_Wk + (size_t)col0 * KDIM;
        out = g_K + (size_t)B_ * E_ + col0;  bias = bk + col0;
    }
    gemm_core<0>(A, W, out, bias, nullptr, bm, 1024);
}

// ---------------------------------------------------------------------------
// Scores: one warp per (b,h); 2-way softmax -> a0 weight only.
// ---------------------------------------------------------------------------
__global__ void k_scores(const __half* __restrict__ Q, const __half* __restrict__ K) {
    int gw   = blockIdx.x * (blockDim.x >> 5) + (threadIdx.x >> 5);
    int lane = threadIdx.x & 31;
    int b = gw >> 3;
    int h = gw & 7;
    if (b >= B_) return;

    const __half2* q2  = reinterpret_cast<const __half2*>(Q + (size_t)b * E_ + h * D_) + lane * 2;
    const __half2* ki2 = reinterpret_cast<const __half2*>(K + (size_t)b * E_ + h * D_) + lane * 2;
    const __half2* ks2 = reinterpret_cast<const __half2*>(K + (size_t)(B_ + b) * E_ + h * D_) + lane * 2;

    float2 qa = __half22float2(q2[0]),  qb = __half22float2(q2[1]);
    float2 ka = __half22float2(ki2[0]), kb = __half22float2(ki2[1]);
    float2 sa = __half22float2(ks2[0]), sb = __half22float2(ks2[1]);

    float d0 = qa.x * ka.x + qa.y * ka.y + qb.x * kb.x + qb.y * kb.y;
    float d1 = qa.x * sa.x + qa.y * sa.y + qb.x * sb.x + qb.y * sb.y;
#pragma unroll
    for (int off = 16; off > 0; off >>= 1) {
        d0 += __shfl_xor_sync(0xffffffffu, d0, off);
        d1 += __shfl_xor_sync(0xffffffffu, d1, off);
    }
    const float scale = 0.08838834764831845f;   // 1/sqrt(128)
    d0 *= scale; d1 *= scale;
    float m  = fmaxf(d0, d1);
    float e0 = __expf(d0 - m), e1 = __expf(d1 - m);
    float a0 = e0 / (e0 + e1);
    if (lane == 0) g_attw[(size_t)b * H_ + h] = a0;
}

// ---------------------------------------------------------------------------
// Fused V-projection + attention combine (R7 fragment-mix — best known):
//   ctx[:, h*128:(h+1)*128] = (a0_h*img + (1-a0_h)*sig) * Wv_h^T + bv_h
// A tiles (img & sig) both staged; mixing done on fragments with per-row
// half2 coefficients (fma pipe, overlaps tensor). 2-stage cp.async.
// ---------------------------------------------------------------------------
constexpr int V_STGH = 3 * A_STG;                    // img + sig + B
constexpr int V_SMEM = 2 * V_STGH * (int)sizeof(__half);  // 110592

__global__ __launch_bounds__(256, 2) void k_vgemm(const float* __restrict__ bv) {
    extern __shared__ __half smem[];

    const int h  = blockIdx.x;
    const int bm = blockIdx.y * BM;
    const int tid  = threadIdx.x;
    const int warp = tid >> 5;
    const int lane = tid & 31;
    const int wm   = (warp & 1) * 64;
    const int wn   = (warp >> 1) * 32;

    const __half* Aimg = g_AB;
    const __half* Asig = g_AB + (size_t)B_ * E_;
    const __half* W    = g_Wv + (size_t)h * 128 * KDIM;

    float acc[4][4][4];
#pragma unroll
    for (int i = 0; i < 4; i++)
#pragma unroll
        for (int j = 0; j < 4; j++)
#pragma unroll
            for (int l = 0; l < 4; l++) acc[i][j][l] = 0.f;

    // per-row mixing coefficients (fragment rows g and g+8 per am)
    uint32_t c0[4][2], c1[4][2];
    {
        const int g = lane >> 2;
#pragma unroll
        for (int am = 0; am < 4; am++) {
            int r0 = bm + wm + am * 16 + g;
            float ca = g_attw[(size_t)r0 * H_ + h];
            float cb = g_attw[(size_t)(r0 + 8) * H_ + h];
            __half2 t;
            t = __float2half2_rn(ca);       c0[am][0] = *reinterpret_cast<uint32_t*>(&t);
            t = __float2half2_rn(1.f - ca); c1[am][0] = *reinterpret_cast<uint32_t*>(&t);
            t = __float2half2_rn(cb);       c0[am][1] = *reinterpret_cast<uint32_t*>(&t);
            t = __float2half2_rn(1.f - cb); c1[am][1] = *reinterpret_cast<uint32_t*>(&t);
        }
    }

    auto load_stage = [&](int stage, int kt) {
        const int k0 = kt * BK;
        __half* si = smem + stage * V_STGH;
        __half* ss = si + A_STG;
        __half* sb = si + 2 * A_STG;
#pragma unroll
        for (int i = 0; i < 12; i++) {
            int id = tid + i * 256;                  // 0..3071
            int row = (id & 1023) >> 3, seg = id & 7;
            if (id < 1024)
                cp16(smem_u32(si + row * LDS + seg * 8),
                     Aimg + (size_t)(bm + row) * KDIM + k0 + seg * 8);
            else if (id < 2048)
                cp16(smem_u32(ss + row * LDS + seg * 8),
                     Asig + (size_t)(bm + row) * KDIM + k0 + seg * 8);
            else
                cp16(smem_u32(sb + row * LDS + seg * 8),
                     W + (size_t)row * KDIM + k0 + seg * 8);
        }
    };

    load_stage(0, 0);
    cp_commit();

    const int a_row = (lane & 15);
    const int a_col = (lane >> 4) * 8;
    const int b_row = ((lane >> 4) << 3) + (lane & 7);
    const int b_col = ((lane >> 3) & 1) * 8;

    for (int kt = 0; kt < KT; kt++) {
        cp_wait<0>();
        __syncthreads();

        if (kt + 1 < KT) load_stage((kt + 1) & 1, kt + 1);
        cp_commit();

        const __half* ai = smem + (kt & 1) * V_STGH;
        const __half* as = ai + A_STG;
        const __half* bs = ai + 2 * A_STG;

#pragma unroll
        for (int kk = 0; kk < 4; kk++) {
            uint32_t bfr[8];
#pragma unroll
            for (int p = 0; p < 2; p++) {
                uint32_t t[4];
                int r = wn + p * 16 + b_row;
                ldmatrix_x4(t, smem_u32(bs + r * LDS + kk * 16 + b_col));
                bfr[4 * p + 0] = t[0]; bfr[4 * p + 1] = t[1];
                bfr[4 * p + 2] = t[2]; bfr[4 * p + 3] = t[3];
            }
#pragma unroll
            for (int am = 0; am < 4; am++) {
                uint32_t fi[4], fs[4], af[4];
                int r = wm + am * 16 + a_row;
                ldmatrix_x4(fi, smem_u32(ai + r * LDS + kk * 16 + a_col));
                ldmatrix_x4(fs, smem_u32(as + r * LDS + kk * 16 + a_col));
#pragma unroll
                for (int j = 0; j < 4; j++) {
                    const int half_sel = j & 1;      // regs 0,2 -> row g; 1,3 -> g+8
                    __half2 i2 = *reinterpret_cast<__half2*>(&fi[j]);
                    __half2 s2 = *reinterpret_cast<__half2*>(&fs[j]);
                    __half2 cc0 = *reinterpret_cast<__half2*>(&c0[am][half_sel]);
                    __half2 cc1 = *reinterpret_cast<__half2*>(&c1[am][half_sel]);
                    __half2 mx = __hfma2(i2, cc0, __hmul2(s2, cc1));
                    af[j] = *reinterpret_cast<uint32_t*>(&mx);
                }
#pragma unroll
                for (int an = 0; an < 4; an++)
                    mma16816(acc[am][an], af, &bfr[2 * an]);
            }
        }
    }

    // Epilogue -> g_ctx (half), bias = bv slice
    const int tr = lane >> 2;
    const int tc = (lane & 3) * 2;
    const float* bh = bv + h * 128;
    __half* outH = g_ctx + h * 128;
#pragma unroll
    for (int am = 0; am < 4; am++) {
#pragma unroll
        for (int an = 0; an < 4; an++) {
            int row0 = bm + wm + am * 16 + tr;
            int cl   = wn + an * 8 + tc;
            float* a = acc[am][an];
            float2 bb = *reinterpret_cast<const float2*>(&bh[cl]);
            *reinterpret_cast<__half2*>(&outH[(size_t)row0 * 1024 + cl]) =
                __floats2half2_rn(a[0] + bb.x, a[1] + bb.y);
            *reinterpret_cast<__half2*>(&outH[(size_t)(row0 + 8) * 1024 + cl]) =
                __floats2half2_rn(a[2] + bb.x, a[3] + bb.y);
        }
    }
}

// ---------------------------------------------------------------------------
// O-projection: fused = ctx * Wo^T + bo + img(fp16)   -> g_fused (fp16)
// ---------------------------------------------------------------------------
__global__ __launch_bounds__(256, 2) void k_ogemm(const float* __restrict__ bo) {
    const int col0 = blockIdx.x * 128;
    const int bm   = blockIdx.y * BM;
    gemm_core<1>(g_ctx, g_Wo + (size_t)col0 * KDIM, g_fused + col0,
                 bo + col0, g_AB + col0, bm, 1024);
}

// ---------------------------------------------------------------------------
// LayerNorm: one warp per row of 1024 halfs (compute in fp32, write fp32).
// ---------------------------------------------------------------------------
__global__ void k_layernorm(const __half* __restrict__ fused,
                            const float* __restrict__ gamma,
                            const float* __restrict__ beta,
                            float* __restrict__ out) {
    int row  = blockIdx.x * (blockDim.x >> 5) + (threadIdx.x >> 5);
    int lane = threadIdx.x & 31;
    if (row >= B_) return;

    const uint4* r4 = reinterpret_cast<const uint4*>(fused + (size_t)row * E_);
    float xs[32];
    float s = 0.f, sq = 0.f;
#pragma unroll
    for (int j = 0; j < 4; j++) {
        uint4 v = r4[lane + 32 * j];          // 8 halfs
        const __half2* h2 = reinterpret_cast<const __half2*>(&v);
#pragma unroll
        for (int t = 0; t < 4; t++) {
            float2 f = __half22float2(h2[t]);
            xs[j * 8 + t * 2]     = f.x;
            xs[j * 8 + t * 2 + 1] = f.y;
            s  += f.x + f.y;
            sq += f.x * f.x + f.y * f.y;
        }
    }
#pragma unroll
    for (int off = 16; off > 0; off >>= 1) {
        s  += __shfl_xor_sync(0xffffffffu, s,  off);
        sq += __shfl_xor_sync(0xffffffffu, sq, off);
    }
    float mean = s * (1.f / E_);
    float var  = sq * (1.f / E_) - mean * mean;
    float rstd = rsqrtf(var + 1e-5f);

    float4* o4 = reinterpret_cast<float4*>(out + (size_t)row * E_);
    const float4* g4 = reinterpret_cast<const float4*>(gamma);
    const float4* b4 = reinterpret_cast<const float4*>(beta);
#pragma unroll
    for (int j = 0; j < 4; j++) {
        int c4 = (lane + 32 * j) * 2;         // float4 index (covers 8 columns)
#pragma unroll
        for (int q = 0; q < 2; q++) {
            float4 g = g4[c4 + q], bb = b4[c4 + q], r;
            const float* x = &xs[j * 8 + q * 4];
            r.x = (x[0] - mean) * rstd * g.x + bb.x;
            r.y = (x[1] - mean) * rstd * g.y + bb.y;
            r.z = (x[2] - mean) * rstd * g.z + bb.z;
            r.w = (x[3] - mean) * rstd * g.w + bb.w;
            o4[c4 + q] = r;
        }
    }
}

// ---------------------------------------------------------------------------
// kernel_launch
// ---------------------------------------------------------------------------
extern "C" void kernel_launch(void* const* d_in, const int* in_sizes, int n_in,
                              void* d_out, int out_size) {
    const float* img   = (const float*)d_in[0];
    const float* sig   = (const float*)d_in[1];
    const float* wq    = (const float*)d_in[2];
    const float* wk    = (const float*)d_in[3];
    const float* wv    = (const float*)d_in[4];
    const float* bq    = (const float*)d_in[5];
    const float* bk    = (const float*)d_in[6];
    const float* bv    = (const float*)d_in[7];
    const float* wo    = (const float*)d_in[8];
    const float* bo    = (const float*)d_in[9];
    const float* gamma = (const float*)d_in[10];
    const float* beta  = (const float*)d_in[11];
    float* out = (float*)d_out;

    void *pQ, *pK, *pFused;
    cudaGetSymbolAddress(&pQ,     g_Q);
    cudaGetSymbolAddress(&pK,     g_K);
    cudaGetSymbolAddress(&pFused, g_fused);

    cudaFuncSetAttribute(k_qk,    cudaFuncAttributeMaxDynamicSharedMemorySize, SMEM_BYTES);
    cudaFuncSetAttribute(k_vgemm, cudaFuncAttributeMaxDynamicSharedMemorySize, V_SMEM);
    cudaFuncSetAttribute(k_ogemm, cudaFuncAttributeMaxDynamicSharedMemorySize, SMEM_BYTES);

    // 1) conversions
    k_convert_all<<<CVT_TOT / 256, 256>>>(img, sig, wq, wk, wv, wo);

    // 2) Q + K_img + K_sig projections (3 GEMM units, one launch)
    k_qk<<<dim3(24, B_ / BM), 256, SMEM_BYTES>>>(bq, bk);

    // 3) attention weights a0[b,h]
    k_scores<<<(B_ * H_) / 8, 256>>>((const __half*)pQ, (const __half*)pK);

    // 4) fused V-projection + combine -> ctx (fragment-mix, best known)
    k_vgemm<<<dim3(H_, B_ / BM), 256, V_SMEM>>>(bv);

    // 5) fused = ctx * Wo^T + bo + img(fp16)  -> fp16
    k_ogemm<<<dim3(E_ / BN, B_ / BM), 256, SMEM_BYTES>>>(bo);

    // 6) LayerNorm (fp16 in, fp32 out)
    k_layernorm<<<B_ / 8, 256>>>((const __half*)pFused, gamma, beta, out);
}

// round 13
// speedup vs baseline: 1.0614x; 1.0154x over previous
#include <cuda_runtime.h>
#include <cuda_fp16.h>
#include <cstdint>

// Problem constants
constexpr int B_ = 16384;
constexpr int E_ = 1024;
constexpr int H_ = 8;
constexpr int D_ = 128;

// ---------------------------------------------------------------------------
// Scratch (static device globals: allocation-free, graph-capture safe)
// ---------------------------------------------------------------------------
__device__ __half g_AB[2u * B_ * E_];           // [image; signal] fp16   (64 MB)
__device__ __half g_Wq[E_ * E_];
__device__ __half g_Wk[E_ * E_];
__device__ __half g_Wv[E_ * E_];
__device__ __half g_Wo[E_ * E_];
__device__ __half g_Q[(size_t)B_ * E_];         // q proj                 (32 MB)
__device__ __half g_K[(size_t)2 * B_ * E_];     // [k_img; k_sig]         (64 MB)
__device__ float  g_attw[(size_t)B_ * H_];      // a0 per (b,h)           (0.5MB)
__device__ __half g_ctx[(size_t)B_ * E_];       //                        (32 MB)
__device__ __half g_fused[(size_t)B_ * E_];     // attn_out + residual    (32 MB, fp16)

// ---------------------------------------------------------------------------
// PTX helpers (sm_80-class only: cp.async / ldmatrix / mma.sync)
// ---------------------------------------------------------------------------
__device__ __forceinline__ uint32_t smem_u32(const void* p) {
    return (uint32_t)__cvta_generic_to_shared(p);
}
__device__ __forceinline__ void cp16(uint32_t s, const void* g) {
    asm volatile("cp.async.cg.shared.global [%0], [%1], 16;\n" :: "r"(s), "l"(g));
}
__device__ __forceinline__ void cp_commit() {
    asm volatile("cp.async.commit_group;\n");
}
template <int N>
__device__ __forceinline__ void cp_wait() {
    asm volatile("cp.async.wait_group %0;\n" :: "n"(N));
}
__device__ __forceinline__ void ldmatrix_x4(uint32_t* r, uint32_t addr) {
    asm volatile("ldmatrix.sync.aligned.m8n8.x4.shared.b16 {%0,%1,%2,%3}, [%4];\n"
                 : "=r"(r[0]), "=r"(r[1]), "=r"(r[2]), "=r"(r[3]) : "r"(addr));
}
__device__ __forceinline__ void mma16816(float* c, const uint32_t* a, const uint32_t* b) {
    asm volatile("mma.sync.aligned.m16n8k16.row.col.f32.f16.f16.f32 "
                 "{%0,%1,%2,%3}, {%4,%5,%6,%7}, {%8,%9}, {%0,%1,%2,%3};\n"
                 : "+f"(c[0]), "+f"(c[1]), "+f"(c[2]), "+f"(c[3])
                 : "r"(a[0]), "r"(a[1]), "r"(a[2]), "r"(a[3]), "r"(b[0]), "r"(b[1]));
}

// ---------------------------------------------------------------------------
// Single conversion kernel (inputs fp32->fp16, weights fp32->fp16)
// ---------------------------------------------------------------------------
constexpr int IN4 = (2 * B_ * E_) / 4;        // 8388608
constexpr int W4  = (4 * E_ * E_) / 4;        // 1048576
constexpr int CVT_TOT = IN4 + W4;             // divisible by 256

__global__ void k_convert_all(const float* __restrict__ img, const float* __restrict__ sig,
                              const float* __restrict__ wq, const float* __restrict__ wk,
                              const float* __restrict__ wv, const float* __restrict__ wo) {
    int i = blockIdx.x * blockDim.x + threadIdx.x;
    if (i < IN4) {
        const int n4 = (B_ * E_) / 4;
        float4 v = (i < n4) ? reinterpret_cast<const float4*>(img)[i]
                            : reinterpret_cast<const float4*>(sig)[i - n4];
        __half* dst = g_AB + (size_t)4 * i;
        *reinterpret_cast<__half2*>(dst)     = __floats2half2_rn(v.x, v.y);
        *reinterpret_cast<__half2*>(dst + 2) = __floats2half2_rn(v.z, v.w);
    } else {
        int j = i - IN4;
        const int per = (E_ * E_) / 4;
        int m = j / per;
        int t = j - m * per;
        const float* src;
        __half* dst;
        if (m == 0)      { src = wq; dst = g_Wq; }
        else if (m == 1) { src = wk; dst = g_Wk; }
        else if (m == 2) { src = wv; dst = g_Wv; }
        else             { src = wo; dst = g_Wo; }
        float4 v = reinterpret_cast<const float4*>(src)[t];
        dst += (size_t)4 * t;
        *reinterpret_cast<__half2*>(dst)     = __floats2half2_rn(v.x, v.y);
        *reinterpret_cast<__half2*>(dst + 2) = __floats2half2_rn(v.z, v.w);
    }
}

// ---------------------------------------------------------------------------
// Shared GEMM core: C[*, cl] = A[M,1024] * W[128 rows,1024]^T (NT), fp16->fp32.
// CTA tile 128x128x64, 3-stage cp.async, 8 warps (2M x 4N), warp 64x32.
// EPI=0: half out = acc + bias[cl]
// EPI=1: half out = acc + bias[cl] + residH[row*ldOut+cl]   (fp16 residual)
// ---------------------------------------------------------------------------
constexpr int BM = 128, BN = 128, BK = 64, STAGES = 3;
constexpr int KDIM = 1024, KT = KDIM / BK;           // 16
constexpr int LDS = BK + 8;                          // 72 halfs / 144B row
constexpr int A_STG = BM * LDS;                      // 9216 halfs
constexpr int STG   = 2 * A_STG;
constexpr int SMEM_BYTES = STAGES * STG * (int)sizeof(__half);   // 110592

template <int EPI>
__device__ __forceinline__ void gemm_core(
    const __half* __restrict__ A,
    const __half* __restrict__ W,
    __half* __restrict__ outH,
    const float* __restrict__ bias,
    const __half* __restrict__ residH,
    int bm, int ldOut)
{
    extern __shared__ __half smem[];

    const int tid  = threadIdx.x;
    const int warp = tid >> 5;
    const int lane = tid & 31;
    const int wm   = (warp & 1) * 64;
    const int wn   = (warp >> 1) * 32;

    float acc[4][4][4];
#pragma unroll
    for (int i = 0; i < 4; i++)
#pragma unroll
        for (int j = 0; j < 4; j++)
#pragma unroll
            for (int l = 0; l < 4; l++) acc[i][j][l] = 0.f;

    auto load_stage = [&](int stage, int kt) {
        const int k0 = kt * BK;
        __half* sa = smem + stage * STG;
        __half* sb = sa + A_STG;
#pragma unroll
        for (int i = 0; i < 8; i++) {
            int id = tid + i * 256;
            if (id < 1024) {
                int row = id >> 3, seg = id & 7;
                cp16(smem_u32(sa + row * LDS + seg * 8),
                     A + (size_t)(bm + row) * KDIM + k0 + seg * 8);
            } else {
                id -= 1024;
                int row = id >> 3, seg = id & 7;
                cp16(smem_u32(sb + row * LDS + seg * 8),
                     W + (size_t)row * KDIM + k0 + seg * 8);
            }
        }
    };

#pragma unroll
    for (int s = 0; s < STAGES - 1; s++) { load_stage(s, s); cp_commit(); }

    const int a_row = (lane & 15);
    const int a_col = (lane >> 4) * 8;
    const int b_row = ((lane >> 4) << 3) + (lane & 7);
    const int b_col = ((lane >> 3) & 1) * 8;

    for (int kt = 0; kt < KT; kt++) {
        cp_wait<STAGES - 2>();
        __syncthreads();

        if (kt + STAGES - 1 < KT) load_stage((kt + STAGES - 1) % STAGES, kt + STAGES - 1);
        cp_commit();

        const __half* as = smem + (kt % STAGES) * STG;
        const __half* bs = as + A_STG;

#pragma unroll
        for (int kk = 0; kk < 4; kk++) {
            uint32_t bfr[8];
#pragma unroll
            for (int p = 0; p < 2; p++) {
                uint32_t t[4];
                int r = wn + p * 16 + b_row;
                ldmatrix_x4(t, smem_u32(bs + r * LDS + kk * 16 + b_col));
                bfr[4 * p + 0] = t[0]; bfr[4 * p + 1] = t[1];
                bfr[4 * p + 2] = t[2]; bfr[4 * p + 3] = t[3];
            }
#pragma unroll
            for (int am = 0; am < 4; am++) {
                uint32_t af[4];
                int r = wm + am * 16 + a_row;
                ldmatrix_x4(af, smem_u32(as + r * LDS + kk * 16 + a_col));
#pragma unroll
                for (int an = 0; an < 4; an++)
                    mma16816(acc[am][an], af, &bfr[2 * an]);
            }
        }
    }

    // Epilogue
    const int tr = lane >> 2;
    const int tc = (lane & 3) * 2;
#pragma unroll
    for (int am = 0; am < 4; am++) {
#pragma unroll
        for (int an = 0; an < 4; an++) {
            int row0 = bm + wm + am * 16 + tr;
            int cl   = wn + an * 8 + tc;
            float* a = acc[am][an];
            float2 bb = *reinterpret_cast<const float2*>(&bias[cl]);
            size_t i0 = (size_t)row0 * ldOut + cl;
            size_t i1 = (size_t)(row0 + 8) * ldOut + cl;
            if (EPI == 0) {
                *reinterpret_cast<__half2*>(&outH[i0]) =
                    __floats2half2_rn(a[0] + bb.x, a[1] + bb.y);
                *reinterpret_cast<__half2*>(&outH[i1]) =
                    __floats2half2_rn(a[2] + bb.x, a[3] + bb.y);
            } else {
                float2 r0 = __half22float2(*reinterpret_cast<const __half2*>(&residH[i0]));
                float2 r1 = __half22float2(*reinterpret_cast<const __half2*>(&residH[i1]));
                *reinterpret_cast<__half2*>(&outH[i0]) =
                    __floats2half2_rn(a[0] + bb.x + r0.x, a[1] + bb.y + r0.y);
                *reinterpret_cast<__half2*>(&outH[i1]) =
                    __floats2half2_rn(a[2] + bb.x + r1.x, a[3] + bb.y + r1.y);
            }
        }
    }
}

// ---------------------------------------------------------------------------
// Fused Q/K projections: one launch covers
//   gx in [0,8)  : Q     = img * Wq^T + bq -> g_Q
//   gx in [8,16) : K_img = img * Wk^T + bk -> g_K rows [0,B)
//   gx in [16,24): K_sig = sig * Wk^T + bk -> g_K rows [B,2B)
// ---------------------------------------------------------------------------
__global__ __launch_bounds__(256, 2) void k_qk(const float* __restrict__ bq,
                                               const float* __restrict__ bk) {
    const int gx = blockIdx.x;
    const int bm = blockIdx.y * BM;

    const __half* A;
    const __half* W;
    __half* out;
    const float* bias;

    if (gx < 8) {
        int col0 = gx * 128;
        A = g_AB;  W = g_Wq + (size_t)col0 * KDIM;
        out = g_Q + col0;  bias = bq + col0;
    } else if (gx < 16) {
        int col0 = (gx - 8) * 128;
        A = g_AB;  W = g_Wk + (size_t)col0 * KDIM;
        out = g_K + col0;  bias = bk + col0;
    } else {
        int col0 = (gx - 16) * 128;
        A = g_AB + (size_t)B_ * E_;  W = g_Wk + (size_t)col0 * KDIM;
        out = g_K + (size_t)B_ * E_ + col0;  bias = bk + col0;
    }
    gemm_core<0>(A, W, out, bias, nullptr, bm, 1024);
}

// ---------------------------------------------------------------------------
// Scores: one warp per (b,h); 2-way softmax -> a0 weight only.
// ---------------------------------------------------------------------------
__global__ void k_scores(const __half* __restrict__ Q, const __half* __restrict__ K) {
    int gw   = blockIdx.x * (blockDim.x >> 5) + (threadIdx.x >> 5);
    int lane = threadIdx.x & 31;
    int b = gw >> 3;
    int h = gw & 7;
    if (b >= B_) return;

    const __half2* q2  = reinterpret_cast<const __half2*>(Q + (size_t)b * E_ + h * D_) + lane * 2;
    const __half2* ki2 = reinterpret_cast<const __half2*>(K + (size_t)b * E_ + h * D_) + lane * 2;
    const __half2* ks2 = reinterpret_cast<const __half2*>(K + (size_t)(B_ + b) * E_ + h * D_) + lane * 2;

    float2 qa = __half22float2(q2[0]),  qb = __half22float2(q2[1]);
    float2 ka = __half22float2(ki2[0]), kb = __half22float2(ki2[1]);
    float2 sa = __half22float2(ks2[0]), sb = __half22float2(ks2[1]);

    float d0 = qa.x * ka.x + qa.y * ka.y + qb.x * kb.x + qb.y * kb.y;
    float d1 = qa.x * sa.x + qa.y * sa.y + qb.x * sb.x + qb.y * sb.y;
#pragma unroll
    for (int off = 16; off > 0; off >>= 1) {
        d0 += __shfl_xor_sync(0xffffffffu, d0, off);
        d1 += __shfl_xor_sync(0xffffffffu, d1, off);
    }
    const float scale = 0.08838834764831845f;   // 1/sqrt(128)
    d0 *= scale; d1 *= scale;
    float m  = fmaxf(d0, d1);
    float e0 = __expf(d0 - m), e1 = __expf(d1 - m);
    float a0 = e0 / (e0 + e1);
    if (lane == 0) g_attw[(size_t)b * H_ + h] = a0;
}

// ---------------------------------------------------------------------------
// Fused V-projection + attention combine (fragment-mix, 4Mx2N warp grid):
//   ctx[:, h*128:(h+1)*128] = (a0_h*img + (1-a0_h)*sig) * Wv_h^T + bv_h
// Warp tile 32x64: halves per-warp A LDSM (the doubled stream) and the
// fragment-mix HFMA2 count vs the 64x32 layout; B LDSM +1KB/warp/kk.
// Per-kk bytes/warp: 5KB -> 4KB  => CTA-kt LDSM 160KB -> 128KB.
// ---------------------------------------------------------------------------
constexpr int V_STGH = 3 * A_STG;                    // img + sig + B
constexpr int V_SMEM = 2 * V_STGH * (int)sizeof(__half);  // 110592

__global__ __launch_bounds__(256, 2) void k_vgemm(const float* __restrict__ bv) {
    extern __shared__ __half smem[];

    const int h  = blockIdx.x;
    const int bm = blockIdx.y * BM;
    const int tid  = threadIdx.x;
    const int warp = tid >> 5;
    const int lane = tid & 31;
    const int wm   = (warp & 3) * 32;      // 4 M-warps
    const int wn   = (warp >> 2) * 64;     // 2 N-warps

    const __half* Aimg = g_AB;
    const __half* Asig = g_AB + (size_t)B_ * E_;
    const __half* W    = g_Wv + (size_t)h * 128 * KDIM;

    float acc[2][8][4];
#pragma unroll
    for (int i = 0; i < 2; i++)
#pragma unroll
        for (int j = 0; j < 8; j++)
#pragma unroll
            for (int l = 0; l < 4; l++) acc[i][j][l] = 0.f;

    // per-row mixing coefficients (fragment rows g and g+8 per am)
    uint32_t c0[2][2], c1[2][2];
    {
        const int g = lane >> 2;
#pragma unroll
        for (int am = 0; am < 2; am++) {
            int r0 = bm + wm + am * 16 + g;
            float ca = g_attw[(size_t)r0 * H_ + h];
            float cb = g_attw[(size_t)(r0 + 8) * H_ + h];
            __half2 t;
            t = __float2half2_rn(ca);       c0[am][0] = *reinterpret_cast<uint32_t*>(&t);
            t = __float2half2_rn(1.f - ca); c1[am][0] = *reinterpret_cast<uint32_t*>(&t);
            t = __float2half2_rn(cb);       c0[am][1] = *reinterpret_cast<uint32_t*>(&t);
            t = __float2half2_rn(1.f - cb); c1[am][1] = *reinterpret_cast<uint32_t*>(&t);
        }
    }

    auto load_stage = [&](int stage, int kt) {
        const int k0 = kt * BK;
        __half* si = smem + stage * V_STGH;
        __half* ss = si + A_STG;
        __half* sb = si + 2 * A_STG;
#pragma unroll
        for (int i = 0; i < 12; i++) {
            int id = tid + i * 256;                  // 0..3071
            int row = (id & 1023) >> 3, seg = id & 7;
            if (id < 1024)
                cp16(smem_u32(si + row * LDS + seg * 8),
                     Aimg + (size_t)(bm + row) * KDIM + k0 + seg * 8);
            else if (id < 2048)
                cp16(smem_u32(ss + row * LDS + seg * 8),
                     Asig + (size_t)(bm + row) * KDIM + k0 + seg * 8);
            else
                cp16(smem_u32(sb + row * LDS + seg * 8),
                     W + (size_t)row * KDIM + k0 + seg * 8);
        }
    };

    load_stage(0, 0);
    cp_commit();

    const int a_row = (lane & 15);
    const int a_col = (lane >> 4) * 8;
    const int b_row = ((lane >> 4) << 3) + (lane & 7);
    const int b_col = ((lane >> 3) & 1) * 8;

    for (int kt = 0; kt < KT; kt++) {
        cp_wait<0>();
        __syncthreads();

        if (kt + 1 < KT) load_stage((kt + 1) & 1, kt + 1);
        cp_commit();

        const __half* ai = smem + (kt & 1) * V_STGH;
        const __half* as = ai + A_STG;
        const __half* bs = ai + 2 * A_STG;

#pragma unroll
        for (int kk = 0; kk < 4; kk++) {
            uint32_t bfr[16];
#pragma unroll
            for (int p = 0; p < 4; p++) {            // 8 n8 tiles = 64 cols
                uint32_t t[4];
                int r = wn + p * 16 + b_row;
                ldmatrix_x4(t, smem_u32(bs + r * LDS + kk * 16 + b_col));
                bfr[4 * p + 0] = t[0]; bfr[4 * p + 1] = t[1];
                bfr[4 * p + 2] = t[2]; bfr[4 * p + 3] = t[3];
            }
#pragma unroll
            for (int am = 0; am < 2; am++) {
                uint32_t fi[4], fs[4], af[4];
                int r = wm + am * 16 + a_row;
                ldmatrix_x4(fi, smem_u32(ai + r * LDS + kk * 16 + a_col));
                ldmatrix_x4(fs, smem_u32(as + r * LDS + kk * 16 + a_col));
#pragma unroll
                for (int j = 0; j < 4; j++) {
                    const int half_sel = j & 1;      // regs 0,2 -> row g; 1,3 -> g+8
                    __half2 i2 = *reinterpret_cast<__half2*>(&fi[j]);
                    __half2 s2 = *reinterpret_cast<__half2*>(&fs[j]);
                    __half2 cc0 = *reinterpret_cast<__half2*>(&c0[am][half_sel]);
                    __half2 cc1 = *reinterpret_cast<__half2*>(&c1[am][half_sel]);
                    __half2 mx = __hfma2(i2, cc0, __hmul2(s2, cc1));
                    af[j] = *reinterpret_cast<uint32_t*>(&mx);
                }
#pragma unroll
                for (int an = 0; an < 8; an++)
                    mma16816(acc[am][an], af, &bfr[2 * an]);
            }
        }
    }

    // Epilogue -> g_ctx (half), bias = bv slice
    const int tr = lane >> 2;
    const int tc = (lane & 3) * 2;
    const float* bh = bv + h * 128;
    __half* outH = g_ctx + h * 128;
#pragma unroll
    for (int am = 0; am < 2; am++) {
#pragma unroll
        for (int an = 0; an < 8; an++) {
            int row0 = bm + wm + am * 16 + tr;
            int cl   = wn + an * 8 + tc;
            float* a = acc[am][an];
            float2 bb = *reinterpret_cast<const float2*>(&bh[cl]);
            *reinterpret_cast<__half2*>(&outH[(size_t)row0 * 1024 + cl]) =
                __floats2half2_rn(a[0] + bb.x, a[1] + bb.y);
            *reinterpret_cast<__half2*>(&outH[(size_t)(row0 + 8) * 1024 + cl]) =
                __floats2half2_rn(a[2] + bb.x, a[3] + bb.y);
        }
    }
}

// ---------------------------------------------------------------------------
// O-projection: fused = ctx * Wo^T + bo + img(fp16)   -> g_fused (fp16)
// ---------------------------------------------------------------------------
__global__ __launch_bounds__(256, 2) void k_ogemm(const float* __restrict__ bo) {
    const int col0 = blockIdx.x * 128;
    const int bm   = blockIdx.y * BM;
    gemm_core<1>(g_ctx, g_Wo + (size_t)col0 * KDIM, g_fused + col0,
                 bo + col0, g_AB + col0, bm, 1024);
}

// ---------------------------------------------------------------------------
// LayerNorm: one warp per row of 1024 halfs (compute in fp32, write fp32).
// ---------------------------------------------------------------------------
__global__ void k_layernorm(const __half* __restrict__ fused,
                            const float* __restrict__ gamma,
                            const float* __restrict__ beta,
                            float* __restrict__ out) {
    int row  = blockIdx.x * (blockDim.x >> 5) + (threadIdx.x >> 5);
    int lane = threadIdx.x & 31;
    if (row >= B_) return;

    const uint4* r4 = reinterpret_cast<const uint4*>(fused + (size_t)row * E_);
    float xs[32];
    float s = 0.f, sq = 0.f;
#pragma unroll
    for (int j = 0; j < 4; j++) {
        uint4 v = r4[lane + 32 * j];          // 8 halfs
        const __half2* h2 = reinterpret_cast<const __half2*>(&v);
#pragma unroll
        for (int t = 0; t < 4; t++) {
            float2 f = __half22float2(h2[t]);
            xs[j * 8 + t * 2]     = f.x;
            xs[j * 8 + t * 2 + 1] = f.y;
            s  += f.x + f.y;
            sq += f.x * f.x + f.y * f.y;
        }
    }
#pragma unroll
    for (int off = 16; off > 0; off >>= 1) {
        s  += __shfl_xor_sync(0xffffffffu, s,  off);
        sq += __shfl_xor_sync(0xffffffffu, sq, off);
    }
    float mean = s * (1.f / E_);
    float var  = sq * (1.f / E_) - mean * mean;
    float rstd = rsqrtf(var + 1e-5f);

    float4* o4 = reinterpret_cast<float4*>(out + (size_t)row * E_);
    const float4* g4 = reinterpret_cast<const float4*>(gamma);
    const float4* b4 = reinterpret_cast<const float4*>(beta);
#pragma unroll
    for (int j = 0; j < 4; j++) {
        int c4 = (lane + 32 * j) * 2;         // float4 index (covers 8 columns)
#pragma unroll
        for (int q = 0; q < 2; q++) {
            float4 g = g4[c4 + q], bb = b4[c4 + q], r;
            const float* x = &xs[j * 8 + q * 4];
            r.x = (x[0] - mean) * rstd * g.x + bb.x;
            r.y = (x[1] - mean) * rstd * g.y + bb.y;
            r.z = (x[2] - mean) * rstd * g.z + bb.z;
            r.w = (x[3] - mean) * rstd * g.w + bb.w;
            o4[c4 + q] = r;
        }
    }
}

// ---------------------------------------------------------------------------
// kernel_launch
// ---------------------------------------------------------------------------
extern "C" void kernel_launch(void* const* d_in, const int* in_sizes, int n_in,
                              void* d_out, int out_size) {
    const float* img   = (const float*)d_in[0];
    const float* sig   = (const float*)d_in[1];
    const float* wq    = (const float*)d_in[2];
    const float* wk    = (const float*)d_in[3];
    const float* wv    = (const float*)d_in[4];
    const float* bq    = (const float*)d_in[5];
    const float* bk    = (const float*)d_in[6];
    const float* bv    = (const float*)d_in[7];
    const float* wo    = (const float*)d_in[8];
    const float* bo    = (const float*)d_in[9];
    const float* gamma = (const float*)d_in[10];
    const float* beta  = (const float*)d_in[11];
    float* out = (float*)d_out;

    void *pQ, *pK, *pFused;
    cudaGetSymbolAddress(&pQ,     g_Q);
    cudaGetSymbolAddress(&pK,     g_K);
    cudaGetSymbolAddress(&pFused, g_fused);

    cudaFuncSetAttribute(k_qk,    cudaFuncAttributeMaxDynamicSharedMemorySize, SMEM_BYTES);
    cudaFuncSetAttribute(k_vgemm, cudaFuncAttributeMaxDynamicSharedMemorySize, V_SMEM);
    cudaFuncSetAttribute(k_ogemm, cudaFuncAttributeMaxDynamicSharedMemorySize, SMEM_BYTES);

    // 1) conversions
    k_convert_all<<<CVT_TOT / 256, 256>>>(img, sig, wq, wk, wv, wo);

    // 2) Q + K_img + K_sig projections (3 GEMM units, one launch)
    k_qk<<<dim3(24, B_ / BM), 256, SMEM_BYTES>>>(bq, bk);

    // 3) attention weights a0[b,h]
    k_scores<<<(B_ * H_) / 8, 256>>>((const __half*)pQ, (const __half*)pK);

    // 4) fused V-projection + combine -> ctx (4Mx2N fragment-mix)
    k_vgemm<<<dim3(H_, B_ / BM), 256, V_SMEM>>>(bv);

    // 5) fused = ctx * Wo^T + bo + img(fp16)  -> fp16
    k_ogemm<<<dim3(E_ / BN, B_ / BM), 256, SMEM_BYTES>>>(bo);

    // 6) LayerNorm (fp16 in, fp32 out)
    k_layernorm<<<B_ / 8, 256>>>((const __half*)pFused, gamma, beta, out);
}

// round 14
// speedup vs baseline: 1.2689x; 1.1955x over previous
#include <cuda_runtime.h>
#include <cuda_fp16.h>
#include <cstdint>

// Problem constants
constexpr int B_ = 16384;
constexpr int E_ = 1024;
constexpr int H_ = 8;
constexpr int D_ = 128;

// ---------------------------------------------------------------------------
// Scratch (static device globals: allocation-free, graph-capture safe)
// ---------------------------------------------------------------------------
__device__ __half g_AB[2u * B_ * E_];           // [image; signal] fp16   (64 MB)
__device__ __half g_D[(size_t)B_ * E_];         // img - sig (fp16)       (32 MB)
__device__ __half g_Wq[E_ * E_];
__device__ __half g_Wk[E_ * E_];
__device__ __half g_Wv[E_ * E_];
__device__ __half g_Wo[E_ * E_];
__device__ __half g_Q[(size_t)B_ * E_];         // q proj                 (32 MB)
__device__ __half g_DK[(size_t)B_ * E_];        // (img-sig)*Wk^T         (32 MB)
__device__ float  g_attw[(size_t)B_ * H_];      // a0 per (b,h)           (0.5MB)
__device__ __half g_ctx[(size_t)B_ * E_];       //                        (32 MB)
__device__ __half g_fused[(size_t)B_ * E_];     // attn_out + residual    (32 MB)
__device__ float  g_zero[128];                  // zero bias (static-zeroed)

// ---------------------------------------------------------------------------
// PTX helpers (sm_80-class only: cp.async / ldmatrix / mma.sync)
// ---------------------------------------------------------------------------
__device__ __forceinline__ uint32_t smem_u32(const void* p) {
    return (uint32_t)__cvta_generic_to_shared(p);
}
__device__ __forceinline__ void cp16(uint32_t s, const void* g) {
    asm volatile("cp.async.cg.shared.global [%0], [%1], 16;\n" :: "r"(s), "l"(g));
}
__device__ __forceinline__ void cp_commit() {
    asm volatile("cp.async.commit_group;\n");
}
template <int N>
__device__ __forceinline__ void cp_wait() {
    asm volatile("cp.async.wait_group %0;\n" :: "n"(N));
}
__device__ __forceinline__ void ldmatrix_x4(uint32_t* r, uint32_t addr) {
    asm volatile("ldmatrix.sync.aligned.m8n8.x4.shared.b16 {%0,%1,%2,%3}, [%4];\n"
                 : "=r"(r[0]), "=r"(r[1]), "=r"(r[2]), "=r"(r[3]) : "r"(addr));
}
__device__ __forceinline__ void mma16816(float* c, const uint32_t* a, const uint32_t* b) {
    asm volatile("mma.sync.aligned.m16n8k16.row.col.f32.f16.f16.f32 "
                 "{%0,%1,%2,%3}, {%4,%5,%6,%7}, {%8,%9}, {%0,%1,%2,%3};\n"
                 : "+f"(c[0]), "+f"(c[1]), "+f"(c[2]), "+f"(c[3])
                 : "r"(a[0]), "r"(a[1]), "r"(a[2]), "r"(a[3]), "r"(b[0]), "r"(b[1]));
}

// ---------------------------------------------------------------------------
// Conversion: inputs fp32->fp16 (+ diff), weights fp32->fp16
// ---------------------------------------------------------------------------
constexpr int N4  = (B_ * E_) / 4;            // 4194304 (paired img/sig)
constexpr int W4  = (4 * E_ * E_) / 4;        // 1048576
constexpr int CVT_TOT = N4 + W4;              // divisible by 256

__global__ void k_convert_all(const float* __restrict__ img, const float* __restrict__ sig,
                              const float* __restrict__ wq, const float* __restrict__ wk,
                              const float* __restrict__ wv, const float* __restrict__ wo) {
    int i = blockIdx.x * blockDim.x + threadIdx.x;
    if (i < N4) {
        float4 a = reinterpret_cast<const float4*>(img)[i];
        float4 b = reinterpret_cast<const float4*>(sig)[i];
        __half* di = g_AB + (size_t)4 * i;
        __half* ds = g_AB + (size_t)B_ * E_ + (size_t)4 * i;
        __half* dd = g_D + (size_t)4 * i;
        *reinterpret_cast<__half2*>(di)     = __floats2half2_rn(a.x, a.y);
        *reinterpret_cast<__half2*>(di + 2) = __floats2half2_rn(a.z, a.w);
        *reinterpret_cast<__half2*>(ds)     = __floats2half2_rn(b.x, b.y);
        *reinterpret_cast<__half2*>(ds + 2) = __floats2half2_rn(b.z, b.w);
        *reinterpret_cast<__half2*>(dd)     = __floats2half2_rn(a.x - b.x, a.y - b.y);
        *reinterpret_cast<__half2*>(dd + 2) = __floats2half2_rn(a.z - b.z, a.w - b.w);
    } else {
        int j = i - N4;
        const int per = (E_ * E_) / 4;
        int m = j / per;
        int t = j - m * per;
        const float* src;
        __half* dst;
        if (m == 0)      { src = wq; dst = g_Wq; }
        else if (m == 1) { src = wk; dst = g_Wk; }
        else if (m == 2) { src = wv; dst = g_Wv; }
        else             { src = wo; dst = g_Wo; }
        float4 v = reinterpret_cast<const float4*>(src)[t];
        dst += (size_t)4 * t;
        *reinterpret_cast<__half2*>(dst)     = __floats2half2_rn(v.x, v.y);
        *reinterpret_cast<__half2*>(dst + 2) = __floats2half2_rn(v.z, v.w);
    }
}

// ---------------------------------------------------------------------------
// Shared GEMM core: C[*, cl] = A[M,1024] * W[128 rows,1024]^T (NT), fp16->fp32.
// CTA tile 128x128x64, 3-stage cp.async, 8 warps (2M x 4N), warp 64x32.
// EPI=0: half out = acc + bias[cl]
// EPI=1: half out = acc + bias[cl] + residH[row*ldOut+cl]   (fp16 residual)
// ---------------------------------------------------------------------------
constexpr int BM = 128, BN = 128, BK = 64, STAGES = 3;
constexpr int KDIM = 1024, KT = KDIM / BK;           // 16
constexpr int LDS = BK + 8;                          // 72 halfs / 144B row
constexpr int A_STG = BM * LDS;                      // 9216 halfs
constexpr int STG   = 2 * A_STG;
constexpr int SMEM_BYTES = STAGES * STG * (int)sizeof(__half);   // 110592

template <int EPI>
__device__ __forceinline__ void gemm_core(
    const __half* __restrict__ A,
    const __half* __restrict__ W,
    __half* __restrict__ outH,
    const float* __restrict__ bias,
    const __half* __restrict__ residH,
    int bm, int ldOut)
{
    extern __shared__ __half smem[];

    const int tid  = threadIdx.x;
    const int warp = tid >> 5;
    const int lane = tid & 31;
    const int wm   = (warp & 1) * 64;
    const int wn   = (warp >> 1) * 32;

    float acc[4][4][4];
#pragma unroll
    for (int i = 0; i < 4; i++)
#pragma unroll
        for (int j = 0; j < 4; j++)
#pragma unroll
            for (int l = 0; l < 4; l++) acc[i][j][l] = 0.f;

    auto load_stage = [&](int stage, int kt) {
        const int k0 = kt * BK;
        __half* sa = smem + stage * STG;
        __half* sb = sa + A_STG;
#pragma unroll
        for (int i = 0; i < 8; i++) {
            int id = tid + i * 256;
            if (id < 1024) {
                int row = id >> 3, seg = id & 7;
                cp16(smem_u32(sa + row * LDS + seg * 8),
                     A + (size_t)(bm + row) * KDIM + k0 + seg * 8);
            } else {
                id -= 1024;
                int row = id >> 3, seg = id & 7;
                cp16(smem_u32(sb + row * LDS + seg * 8),
                     W + (size_t)row * KDIM + k0 + seg * 8);
            }
        }
    };

#pragma unroll
    for (int s = 0; s < STAGES - 1; s++) { load_stage(s, s); cp_commit(); }

    const int a_row = (lane & 15);
    const int a_col = (lane >> 4) * 8;
    const int b_row = ((lane >> 4) << 3) + (lane & 7);
    const int b_col = ((lane >> 3) & 1) * 8;

    for (int kt = 0; kt < KT; kt++) {
        cp_wait<STAGES - 2>();
        __syncthreads();

        if (kt + STAGES - 1 < KT) load_stage((kt + STAGES - 1) % STAGES, kt + STAGES - 1);
        cp_commit();

        const __half* as = smem + (kt % STAGES) * STG;
        const __half* bs = as + A_STG;

#pragma unroll
        for (int kk = 0; kk < 4; kk++) {
            uint32_t bfr[8];
#pragma unroll
            for (int p = 0; p < 2; p++) {
                uint32_t t[4];
                int r = wn + p * 16 + b_row;
                ldmatrix_x4(t, smem_u32(bs + r * LDS + kk * 16 + b_col));
                bfr[4 * p + 0] = t[0]; bfr[4 * p + 1] = t[1];
                bfr[4 * p + 2] = t[2]; bfr[4 * p + 3] = t[3];
            }
#pragma unroll
            for (int am = 0; am < 4; am++) {
                uint32_t af[4];
                int r = wm + am * 16 + a_row;
                ldmatrix_x4(af, smem_u32(as + r * LDS + kk * 16 + a_col));
#pragma unroll
                for (int an = 0; an < 4; an++)
                    mma16816(acc[am][an], af, &bfr[2 * an]);
            }
        }
    }

    // Epilogue
    const int tr = lane >> 2;
    const int tc = (lane & 3) * 2;
#pragma unroll
    for (int am = 0; am < 4; am++) {
#pragma unroll
        for (int an = 0; an < 4; an++) {
            int row0 = bm + wm + am * 16 + tr;
            int cl   = wn + an * 8 + tc;
            float* a = acc[am][an];
            float2 bb = *reinterpret_cast<const float2*>(&bias[cl]);
            size_t i0 = (size_t)row0 * ldOut + cl;
            size_t i1 = (size_t)(row0 + 8) * ldOut + cl;
            if (EPI == 0) {
                *reinterpret_cast<__half2*>(&outH[i0]) =
                    __floats2half2_rn(a[0] + bb.x, a[1] + bb.y);
                *reinterpret_cast<__half2*>(&outH[i1]) =
                    __floats2half2_rn(a[2] + bb.x, a[3] + bb.y);
            } else {
                float2 r0 = __half22float2(*reinterpret_cast<const __half2*>(&residH[i0]));
                float2 r1 = __half22float2(*reinterpret_cast<const __half2*>(&residH[i1]));
                *reinterpret_cast<__half2*>(&outH[i0]) =
                    __floats2half2_rn(a[0] + bb.x + r0.x, a[1] + bb.y + r0.y);
                *reinterpret_cast<__half2*>(&outH[i1]) =
                    __floats2half2_rn(a[2] + bb.x + r1.x, a[3] + bb.y + r1.y);
            }
        }
    }
}

// ---------------------------------------------------------------------------
// Fused Q/DK projections: one launch covers
//   gx in [0,8)  : Q  = img * Wq^T + bq        -> g_Q
//   gx in [8,16) : DK = (img-sig) * Wk^T + 0   -> g_DK   (bk cancels in d0-d1)
// ---------------------------------------------------------------------------
__global__ __launch_bounds__(256, 2) void k_qk(const float* __restrict__ bq) {
    const int gx = blockIdx.x;
    const int bm = blockIdx.y * BM;

    const __half* A;
    const __half* W;
    __half* out;
    const float* bias;

    if (gx < 8) {
        int col0 = gx * 128;
        A = g_AB;  W = g_Wq + (size_t)col0 * KDIM;
        out = g_Q + col0;  bias = bq + col0;
    } else {
        int col0 = (gx - 8) * 128;
        A = g_D;   W = g_Wk + (size_t)col0 * KDIM;
        out = g_DK + col0;  bias = g_zero;
    }
    gemm_core<0>(A, W, out, bias, nullptr, bm, 1024);
}

// ---------------------------------------------------------------------------
// Scores: one warp per (b,h); a0 = sigmoid(scale * q_h . dk_h)
// ---------------------------------------------------------------------------
__global__ void k_scores(const __half* __restrict__ Q, const __half* __restrict__ DK) {
    int gw   = blockIdx.x * (blockDim.x >> 5) + (threadIdx.x >> 5);
    int lane = threadIdx.x & 31;
    int b = gw >> 3;
    int h = gw & 7;
    if (b >= B_) return;

    const __half2* q2 = reinterpret_cast<const __half2*>(Q  + (size_t)b * E_ + h * D_) + lane * 2;
    const __half2* d2 = reinterpret_cast<const __half2*>(DK + (size_t)b * E_ + h * D_) + lane * 2;

    float2 qa = __half22float2(q2[0]), qb = __half22float2(q2[1]);
    float2 da = __half22float2(d2[0]), db = __half22float2(d2[1]);

    float d = qa.x * da.x + qa.y * da.y + qb.x * db.x + qb.y * db.y;
#pragma unroll
    for (int off = 16; off > 0; off >>= 1)
        d += __shfl_xor_sync(0xffffffffu, d, off);

    const float scale = 0.08838834764831845f;   // 1/sqrt(128)
    float a0 = 1.f / (1.f + __expf(-scale * d));
    if (lane == 0) g_attw[(size_t)b * H_ + h] = a0;
}

// ---------------------------------------------------------------------------
// Fused V-projection + attention combine (fragment-mix, 4Mx2N warp grid):
//   ctx[:, h*128:(h+1)*128] = (a0_h*img + (1-a0_h)*sig) * Wv_h^T + bv_h
// ---------------------------------------------------------------------------
constexpr int V_STGH = 3 * A_STG;                    // img + sig + B
constexpr int V_SMEM = 2 * V_STGH * (int)sizeof(__half);  // 110592

__global__ __launch_bounds__(256, 2) void k_vgemm(const float* __restrict__ bv) {
    extern __shared__ __half smem[];

    const int h  = blockIdx.x;
    const int bm = blockIdx.y * BM;
    const int tid  = threadIdx.x;
    const int warp = tid >> 5;
    const int lane = tid & 31;
    const int wm   = (warp & 3) * 32;      // 4 M-warps
    const int wn   = (warp >> 2) * 64;     // 2 N-warps

    const __half* Aimg = g_AB;
    const __half* Asig = g_AB + (size_t)B_ * E_;
    const __half* W    = g_Wv + (size_t)h * 128 * KDIM;

    float acc[2][8][4];
#pragma unroll
    for (int i = 0; i < 2; i++)
#pragma unroll
        for (int j = 0; j < 8; j++)
#pragma unroll
            for (int l = 0; l < 4; l++) acc[i][j][l] = 0.f;

    // per-row mixing coefficients (fragment rows g and g+8 per am)
    uint32_t c0[2][2], c1[2][2];
    {
        const int g = lane >> 2;
#pragma unroll
        for (int am = 0; am < 2; am++) {
            int r0 = bm + wm + am * 16 + g;
            float ca = g_attw[(size_t)r0 * H_ + h];
            float cb = g_attw[(size_t)(r0 + 8) * H_ + h];
            __half2 t;
            t = __float2half2_rn(ca);       c0[am][0] = *reinterpret_cast<uint32_t*>(&t);
            t = __float2half2_rn(1.f - ca); c1[am][0] = *reinterpret_cast<uint32_t*>(&t);
            t = __float2half2_rn(cb);       c0[am][1] = *reinterpret_cast<uint32_t*>(&t);
            t = __float2half2_rn(1.f - cb); c1[am][1] = *reinterpret_cast<uint32_t*>(&t);
        }
    }

    auto load_stage = [&](int stage, int kt) {
        const int k0 = kt * BK;
        __half* si = smem + stage * V_STGH;
        __half* ss = si + A_STG;
        __half* sb = si + 2 * A_STG;
#pragma unroll
        for (int i = 0; i < 12; i++) {
            int id = tid + i * 256;                  // 0..3071
            int row = (id & 1023) >> 3, seg = id & 7;
            if (id < 1024)
                cp16(smem_u32(si + row * LDS + seg * 8),
                     Aimg + (size_t)(bm + row) * KDIM + k0 + seg * 8);
            else if (id < 2048)
                cp16(smem_u32(ss + row * LDS + seg * 8),
                     Asig + (size_t)(bm + row) * KDIM + k0 + seg * 8);
            else
                cp16(smem_u32(sb + row * LDS + seg * 8),
                     W + (size_t)row * KDIM + k0 + seg * 8);
        }
    };

    load_stage(0, 0);
    cp_commit();

    const int a_row = (lane & 15);
    const int a_col = (lane >> 4) * 8;
    const int b_row = ((lane >> 4) << 3) + (lane & 7);
    const int b_col = ((lane >> 3) & 1) * 8;

    for (int kt = 0; kt < KT; kt++) {
        cp_wait<0>();
        __syncthreads();

        if (kt + 1 < KT) load_stage((kt + 1) & 1, kt + 1);
        cp_commit();

        const __half* ai = smem + (kt & 1) * V_STGH;
        const __half* as = ai + A_STG;
        const __half* bs = ai + 2 * A_STG;

#pragma unroll
        for (int kk = 0; kk < 4; kk++) {
            uint32_t bfr[16];
#pragma unroll
            for (int p = 0; p < 4; p++) {            // 8 n8 tiles = 64 cols
                uint32_t t[4];
                int r = wn + p * 16 + b_row;
                ldmatrix_x4(t, smem_u32(bs + r * LDS + kk * 16 + b_col));
                bfr[4 * p + 0] = t[0]; bfr[4 * p + 1] = t[1];
                bfr[4 * p + 2] = t[2]; bfr[4 * p + 3] = t[3];
            }
#pragma unroll
            for (int am = 0; am < 2; am++) {
                uint32_t fi[4], fs[4], af[4];
                int r = wm + am * 16 + a_row;
                ldmatrix_x4(fi, smem_u32(ai + r * LDS + kk * 16 + a_col));
                ldmatrix_x4(fs, smem_u32(as + r * LDS + kk * 16 + a_col));
#pragma unroll
                for (int j = 0; j < 4; j++) {
                    const int half_sel = j & 1;      // regs 0,2 -> row g; 1,3 -> g+8
                    __half2 i2 = *reinterpret_cast<__half2*>(&fi[j]);
                    __half2 s2 = *reinterpret_cast<__half2*>(&fs[j]);
                    __half2 cc0 = *reinterpret_cast<__half2*>(&c0[am][half_sel]);
                    __half2 cc1 = *reinterpret_cast<__half2*>(&c1[am][half_sel]);
                    __half2 mx = __hfma2(i2, cc0, __hmul2(s2, cc1));
                    af[j] = *reinterpret_cast<uint32_t*>(&mx);
                }
#pragma unroll
                for (int an = 0; an < 8; an++)
                    mma16816(acc[am][an], af, &bfr[2 * an]);
            }
        }
    }

    // Epilogue -> g_ctx (half), bias = bv slice
    const int tr = lane >> 2;
    const int tc = (lane & 3) * 2;
    const float* bh = bv + h * 128;
    __half* outH = g_ctx + h * 128;
#pragma unroll
    for (int am = 0; am < 2; am++) {
#pragma unroll
        for (int an = 0; an < 8; an++) {
            int row0 = bm + wm + am * 16 + tr;
            int cl   = wn + an * 8 + tc;
            float* a = acc[am][an];
            float2 bb = *reinterpret_cast<const float2*>(&bh[cl]);
            *reinterpret_cast<__half2*>(&outH[(size_t)row0 * 1024 + cl]) =
                __floats2half2_rn(a[0] + bb.x, a[1] + bb.y);
            *reinterpret_cast<__half2*>(&outH[(size_t)(row0 + 8) * 1024 + cl]) =
                __floats2half2_rn(a[2] + bb.x, a[3] + bb.y);
        }
    }
}

// ---------------------------------------------------------------------------
// O-projection: fused = ctx * Wo^T + bo + img(fp16)   -> g_fused (fp16)
// ---------------------------------------------------------------------------
__global__ __launch_bounds__(256, 2) void k_ogemm(const float* __restrict__ bo) {
    const int col0 = blockIdx.x * 128;
    const int bm   = blockIdx.y * BM;
    gemm_core<1>(g_ctx, g_Wo + (size_t)col0 * KDIM, g_fused + col0,
                 bo + col0, g_AB + col0, bm, 1024);
}

// ---------------------------------------------------------------------------
// LayerNorm: one warp per row of 1024 halfs (compute in fp32, write fp32).
// ---------------------------------------------------------------------------
__global__ void k_layernorm(const __half* __restrict__ fused,
                            const float* __restrict__ gamma,
                            const float* __restrict__ beta,
                            float* __restrict__ out) {
    int row  = blockIdx.x * (blockDim.x >> 5) + (threadIdx.x >> 5);
    int lane = threadIdx.x & 31;
    if (row >= B_) return;

    const uint4* r4 = reinterpret_cast<const uint4*>(fused + (size_t)row * E_);
    float xs[32];
    float s = 0.f, sq = 0.f;
#pragma unroll
    for (int j = 0; j < 4; j++) {
        uint4 v = r4[lane + 32 * j];          // 8 halfs
        const __half2* h2 = reinterpret_cast<const __half2*>(&v);
#pragma unroll
        for (int t = 0; t < 4; t++) {
            float2 f = __half22float2(h2[t]);
            xs[j * 8 + t * 2]     = f.x;
            xs[j * 8 + t * 2 + 1] = f.y;
            s  += f.x + f.y;
            sq += f.x * f.x + f.y * f.y;
        }
    }
#pragma unroll
    for (int off = 16; off > 0; off >>= 1) {
        s  += __shfl_xor_sync(0xffffffffu, s,  off);
        sq += __shfl_xor_sync(0xffffffffu, sq, off);
    }
    float mean = s * (1.f / E_);
    float var  = sq * (1.f / E_) - mean * mean;
    float rstd = rsqrtf(var + 1e-5f);

    float4* o4 = reinterpret_cast<float4*>(out + (size_t)row * E_);
    const float4* g4 = reinterpret_cast<const float4*>(gamma);
    const float4* b4 = reinterpret_cast<const float4*>(beta);
#pragma unroll
    for (int j = 0; j < 4; j++) {
        int c4 = (lane + 32 * j) * 2;         // float4 index (covers 8 columns)
#pragma unroll
        for (int q = 0; q < 2; q++) {
            float4 g = g4[c4 + q], bb = b4[c4 + q], r;
            const float* x = &xs[j * 8 + q * 4];
            r.x = (x[0] - mean) * rstd * g.x + bb.x;
            r.y = (x[1] - mean) * rstd * g.y + bb.y;
            r.z = (x[2] - mean) * rstd * g.z + bb.z;
            r.w = (x[3] - mean) * rstd * g.w + bb.w;
            o4[c4 + q] = r;
        }
    }
}

// ---------------------------------------------------------------------------
// kernel_launch
// ---------------------------------------------------------------------------
extern "C" void kernel_launch(void* const* d_in, const int* in_sizes, int n_in,
                              void* d_out, int out_size) {
    const float* img   = (const float*)d_in[0];
    const float* sig   = (const float*)d_in[1];
    const float* wq    = (const float*)d_in[2];
    const float* wk    = (const float*)d_in[3];
    const float* wv    = (const float*)d_in[4];
    const float* bq    = (const float*)d_in[5];
    const float* bk    = (const float*)d_in[6];   // unused: cancels in score diff
    const float* bv    = (const float*)d_in[7];
    const float* wo    = (const float*)d_in[8];
    const float* bo    = (const float*)d_in[9];
    const float* gamma = (const float*)d_in[10];
    const float* beta  = (const float*)d_in[11];
    float* out = (float*)d_out;
    (void)bk;

    void *pQ, *pDK, *pFused;
    cudaGetSymbolAddress(&pQ,     g_Q);
    cudaGetSymbolAddress(&pDK,    g_DK);
    cudaGetSymbolAddress(&pFused, g_fused);

    cudaFuncSetAttribute(k_qk,    cudaFuncAttributeMaxDynamicSharedMemorySize, SMEM_BYTES);
    cudaFuncSetAttribute(k_vgemm, cudaFuncAttributeMaxDynamicSharedMemorySize, V_SMEM);
    cudaFuncSetAttribute(k_ogemm, cudaFuncAttributeMaxDynamicSharedMemorySize, SMEM_BYTES);

    // 1) conversions (+ img-sig diff)
    k_convert_all<<<CVT_TOT / 256, 256>>>(img, sig, wq, wk, wv, wo);

    // 2) Q + DK projections (2 GEMM units, one launch)
    k_qk<<<dim3(16, B_ / BM), 256, SMEM_BYTES>>>(bq);

    // 3) attention weights a0[b,h] = sigmoid(scale * q.dk)
    k_scores<<<(B_ * H_) / 8, 256>>>((const __half*)pQ, (const __half*)pDK);

    // 4) fused V-projection + combine -> ctx (4Mx2N fragment-mix)
    k_vgemm<<<dim3(H_, B_ / BM), 256, V_SMEM>>>(bv);

    // 5) fused = ctx * Wo^T + bo + img(fp16)  -> fp16
    k_ogemm<<<dim3(E_ / BN, B_ / BM), 256, SMEM_BYTES>>>(bo);

    // 6) LayerNorm (fp16 in, fp32 out)
    k_layernorm<<<B_ / 8, 256>>>((const __half*)pFused, gamma, beta, out);
}

// round 15
// speedup vs baseline: 1.3247x; 1.0440x over previous
#include <cuda_runtime.h>
#include <cuda_fp16.h>
#include <cstdint>

// Problem constants
constexpr int B_ = 16384;
constexpr int E_ = 1024;
constexpr int H_ = 8;
constexpr int D_ = 128;

// ---------------------------------------------------------------------------
// Scratch (static device globals: allocation-free, graph-capture safe)
// ---------------------------------------------------------------------------
__device__ __half g_AB[2u * B_ * E_];           // [image; signal] fp16   (64 MB)
__device__ __half g_D[(size_t)B_ * E_];         // img - sig (fp16)       (32 MB)
__device__ __half g_Wq[E_ * E_];
__device__ __half g_Wk[E_ * E_];
__device__ __half g_Wv[E_ * E_];
__device__ __half g_Wo[E_ * E_];
__device__ float  g_attw[(size_t)B_ * H_];      // a0 per (b,h)           (0.5MB)
__device__ __half g_ctx[(size_t)B_ * E_];       //                        (32 MB)
__device__ __half g_fused[(size_t)B_ * E_];     // attn_out + residual    (32 MB)

// ---------------------------------------------------------------------------
// PTX helpers (sm_80-class only: cp.async / ldmatrix / mma.sync)
// ---------------------------------------------------------------------------
__device__ __forceinline__ uint32_t smem_u32(const void* p) {
    return (uint32_t)__cvta_generic_to_shared(p);
}
__device__ __forceinline__ void cp16(uint32_t s, const void* g) {
    asm volatile("cp.async.cg.shared.global [%0], [%1], 16;\n" :: "r"(s), "l"(g));
}
__device__ __forceinline__ void cp_commit() {
    asm volatile("cp.async.commit_group;\n");
}
template <int N>
__device__ __forceinline__ void cp_wait() {
    asm volatile("cp.async.wait_group %0;\n" :: "n"(N));
}
__device__ __forceinline__ void ldmatrix_x4(uint32_t* r, uint32_t addr) {
    asm volatile("ldmatrix.sync.aligned.m8n8.x4.shared.b16 {%0,%1,%2,%3}, [%4];\n"
                 : "=r"(r[0]), "=r"(r[1]), "=r"(r[2]), "=r"(r[3]) : "r"(addr));
}
__device__ __forceinline__ void mma16816(float* c, const uint32_t* a, const uint32_t* b) {
    asm volatile("mma.sync.aligned.m16n8k16.row.col.f32.f16.f16.f32 "
                 "{%0,%1,%2,%3}, {%4,%5,%6,%7}, {%8,%9}, {%0,%1,%2,%3};\n"
                 : "+f"(c[0]), "+f"(c[1]), "+f"(c[2]), "+f"(c[3])
                 : "r"(a[0]), "r"(a[1]), "r"(a[2]), "r"(a[3]), "r"(b[0]), "r"(b[1]));
}

// ---------------------------------------------------------------------------
// Conversion: inputs fp32->fp16 (+ diff), weights fp32->fp16
// ---------------------------------------------------------------------------
constexpr int N4  = (B_ * E_) / 4;            // 4194304 (paired img/sig)
constexpr int W4  = (4 * E_ * E_) / 4;        // 1048576
constexpr int CVT_TOT = N4 + W4;              // divisible by 256

__global__ void k_convert_all(const float* __restrict__ img, const float* __restrict__ sig,
                              const float* __restrict__ wq, const float* __restrict__ wk,
                              const float* __restrict__ wv, const float* __restrict__ wo) {
    int i = blockIdx.x * blockDim.x + threadIdx.x;
    if (i < N4) {
        float4 a = reinterpret_cast<const float4*>(img)[i];
        float4 b = reinterpret_cast<const float4*>(sig)[i];
        __half* di = g_AB + (size_t)4 * i;
        __half* ds = g_AB + (size_t)B_ * E_ + (size_t)4 * i;
        __half* dd = g_D + (size_t)4 * i;
        *reinterpret_cast<__half2*>(di)     = __floats2half2_rn(a.x, a.y);
        *reinterpret_cast<__half2*>(di + 2) = __floats2half2_rn(a.z, a.w);
        *reinterpret_cast<__half2*>(ds)     = __floats2half2_rn(b.x, b.y);
        *reinterpret_cast<__half2*>(ds + 2) = __floats2half2_rn(b.z, b.w);
        *reinterpret_cast<__half2*>(dd)     = __floats2half2_rn(a.x - b.x, a.y - b.y);
        *reinterpret_cast<__half2*>(dd + 2) = __floats2half2_rn(a.z - b.z, a.w - b.w);
    } else {
        int j = i - N4;
        const int per = (E_ * E_) / 4;
        int m = j / per;
        int t = j - m * per;
        const float* src;
        __half* dst;
        if (m == 0)      { src = wq; dst = g_Wq; }
        else if (m == 1) { src = wk; dst = g_Wk; }
        else if (m == 2) { src = wv; dst = g_Wv; }
        else             { src = wo; dst = g_Wo; }
        float4 v = reinterpret_cast<const float4*>(src)[t];
        dst += (size_t)4 * t;
        *reinterpret_cast<__half2*>(dst)     = __floats2half2_rn(v.x, v.y);
        *reinterpret_cast<__half2*>(dst + 2) = __floats2half2_rn(v.z, v.w);
    }
}

// ---------------------------------------------------------------------------
// Shared tiling constants
// ---------------------------------------------------------------------------
constexpr int BM = 128, BN = 128, BK = 64, STAGES = 3;
constexpr int KDIM = 1024, KT = KDIM / BK;           // 16
constexpr int LDS = BK + 8;                          // 72 halfs / 144B row
constexpr int A_STG = BM * LDS;                      // 9216 halfs
constexpr int STG   = 2 * A_STG;
constexpr int SMEM_BYTES = STAGES * STG * (int)sizeof(__half);   // 110592

// ---------------------------------------------------------------------------
// GEMM core (EPI=1 only now): half out = acc + bias[cl] + residH (fp16)
// ---------------------------------------------------------------------------
template <int EPI>
__device__ __forceinline__ void gemm_core(
    const __half* __restrict__ A,
    const __half* __restrict__ W,
    __half* __restrict__ outH,
    const float* __restrict__ bias,
    const __half* __restrict__ residH,
    int bm, int ldOut)
{
    extern __shared__ __half smem[];

    const int tid  = threadIdx.x;
    const int warp = tid >> 5;
    const int lane = tid & 31;
    const int wm   = (warp & 1) * 64;
    const int wn   = (warp >> 1) * 32;

    float acc[4][4][4];
#pragma unroll
    for (int i = 0; i < 4; i++)
#pragma unroll
        for (int j = 0; j < 4; j++)
#pragma unroll
            for (int l = 0; l < 4; l++) acc[i][j][l] = 0.f;

    auto load_stage = [&](int stage, int kt) {
        const int k0 = kt * BK;
        __half* sa = smem + stage * STG;
        __half* sb = sa + A_STG;
#pragma unroll
        for (int i = 0; i < 8; i++) {
            int id = tid + i * 256;
            if (id < 1024) {
                int row = id >> 3, seg = id & 7;
                cp16(smem_u32(sa + row * LDS + seg * 8),
                     A + (size_t)(bm + row) * KDIM + k0 + seg * 8);
            } else {
                id -= 1024;
                int row = id >> 3, seg = id & 7;
                cp16(smem_u32(sb + row * LDS + seg * 8),
                     W + (size_t)row * KDIM + k0 + seg * 8);
            }
        }
    };

#pragma unroll
    for (int s = 0; s < STAGES - 1; s++) { load_stage(s, s); cp_commit(); }

    const int a_row = (lane & 15);
    const int a_col = (lane >> 4) * 8;
    const int b_row = ((lane >> 4) << 3) + (lane & 7);
    const int b_col = ((lane >> 3) & 1) * 8;

    for (int kt = 0; kt < KT; kt++) {
        cp_wait<STAGES - 2>();
        __syncthreads();

        if (kt + STAGES - 1 < KT) load_stage((kt + STAGES - 1) % STAGES, kt + STAGES - 1);
        cp_commit();

        const __half* as = smem + (kt % STAGES) * STG;
        const __half* bs = as + A_STG;

#pragma unroll
        for (int kk = 0; kk < 4; kk++) {
            uint32_t bfr[8];
#pragma unroll
            for (int p = 0; p < 2; p++) {
                uint32_t t[4];
                int r = wn + p * 16 + b_row;
                ldmatrix_x4(t, smem_u32(bs + r * LDS + kk * 16 + b_col));
                bfr[4 * p + 0] = t[0]; bfr[4 * p + 1] = t[1];
                bfr[4 * p + 2] = t[2]; bfr[4 * p + 3] = t[3];
            }
#pragma unroll
            for (int am = 0; am < 4; am++) {
                uint32_t af[4];
                int r = wm + am * 16 + a_row;
                ldmatrix_x4(af, smem_u32(as + r * LDS + kk * 16 + a_col));
#pragma unroll
                for (int an = 0; an < 4; an++)
                    mma16816(acc[am][an], af, &bfr[2 * an]);
            }
        }
    }

    const int tr = lane >> 2;
    const int tc = (lane & 3) * 2;
#pragma unroll
    for (int am = 0; am < 4; am++) {
#pragma unroll
        for (int an = 0; an < 4; an++) {
            int row0 = bm + wm + am * 16 + tr;
            int cl   = wn + an * 8 + tc;
            float* a = acc[am][an];
            float2 bb = *reinterpret_cast<const float2*>(&bias[cl]);
            size_t i0 = (size_t)row0 * ldOut + cl;
            size_t i1 = (size_t)(row0 + 8) * ldOut + cl;
            float2 r0 = __half22float2(*reinterpret_cast<const __half2*>(&residH[i0]));
            float2 r1 = __half22float2(*reinterpret_cast<const __half2*>(&residH[i1]));
            *reinterpret_cast<__half2*>(&outH[i0]) =
                __floats2half2_rn(a[0] + bb.x + r0.x, a[1] + bb.y + r0.y);
            *reinterpret_cast<__half2*>(&outH[i1]) =
                __floats2half2_rn(a[2] + bb.x + r1.x, a[3] + bb.y + r1.y);
        }
    }
}

// ---------------------------------------------------------------------------
// Fused Q + DK + score kernel. Grid (H_, 128).
// Pass 1: Qtile = img * Wq_h^T + bq -> smem qbuf (fp16, per-thread fragments)
// Pass 2: DKtile = diff * Wk_h^T; dot each fragment against parked Q value;
//         shfl-reduce over tc lanes, atomicAdd into rowsum[128];
//         a0 = sigmoid(scale * rowsum) -> g_attw.   (bk cancels in the diff)
// 2-stage cp.async pipeline (smem: 2*STG + qbuf + rowsum = ~107 KB).
// ---------------------------------------------------------------------------
constexpr int QLD = 136;                              // qbuf row stride (halfs)
constexpr int QS_SMEM = (2 * STG + 128 * QLD) * (int)sizeof(__half) + 512;

__global__ __launch_bounds__(256, 2) void k_qkscore(const float* __restrict__ bq) {
    extern __shared__ __half smem[];
    __half* qbuf   = smem + 2 * STG;
    float*  rowsum = reinterpret_cast<float*>(smem + 2 * STG + 128 * QLD);

    const int h  = blockIdx.x;
    const int bm = blockIdx.y * BM;
    const int tid  = threadIdx.x;
    const int warp = tid >> 5;
    const int lane = tid & 31;
    const int wm   = (warp & 1) * 64;
    const int wn   = (warp >> 1) * 32;

    if (tid < 128) rowsum[tid] = 0.f;

    const __half* Wq = g_Wq + (size_t)h * 128 * KDIM;
    const __half* Wk = g_Wk + (size_t)h * 128 * KDIM;

    const int a_row = (lane & 15);
    const int a_col = (lane >> 4) * 8;
    const int b_row = ((lane >> 4) << 3) + (lane & 7);
    const int b_col = ((lane >> 3) & 1) * 8;
    const int tr = lane >> 2;
    const int tc = (lane & 3) * 2;

    float acc[4][4][4];

    auto load_stage = [&](int stage, int kt, const __half* A, const __half* W) {
        const int k0 = kt * BK;
        __half* sa = smem + stage * STG;
        __half* sb = sa + A_STG;
#pragma unroll
        for (int i = 0; i < 8; i++) {
            int id = tid + i * 256;
            if (id < 1024) {
                int row = id >> 3, seg = id & 7;
                cp16(smem_u32(sa + row * LDS + seg * 8),
                     A + (size_t)(bm + row) * KDIM + k0 + seg * 8);
            } else {
                id -= 1024;
                int row = id >> 3, seg = id & 7;
                cp16(smem_u32(sb + row * LDS + seg * 8),
                     W + (size_t)row * KDIM + k0 + seg * 8);
            }
        }
    };

    auto gemm_pass = [&](const __half* A, const __half* W) {
#pragma unroll
        for (int i = 0; i < 4; i++)
#pragma unroll
            for (int j = 0; j < 4; j++)
#pragma unroll
                for (int l = 0; l < 4; l++) acc[i][j][l] = 0.f;

        load_stage(0, 0, A, W);
        cp_commit();

        for (int kt = 0; kt < KT; kt++) {
            cp_wait<0>();
            __syncthreads();

            if (kt + 1 < KT) load_stage((kt + 1) & 1, kt + 1, A, W);
            cp_commit();

            const __half* as = smem + (kt & 1) * STG;
            const __half* bs = as + A_STG;

#pragma unroll
            for (int kk = 0; kk < 4; kk++) {
                uint32_t bfr[8];
#pragma unroll
                for (int p = 0; p < 2; p++) {
                    uint32_t t[4];
                    int r = wn + p * 16 + b_row;
                    ldmatrix_x4(t, smem_u32(bs + r * LDS + kk * 16 + b_col));
                    bfr[4 * p + 0] = t[0]; bfr[4 * p + 1] = t[1];
                    bfr[4 * p + 2] = t[2]; bfr[4 * p + 3] = t[3];
                }
#pragma unroll
                for (int am = 0; am < 4; am++) {
                    uint32_t af[4];
                    int r = wm + am * 16 + a_row;
                    ldmatrix_x4(af, smem_u32(as + r * LDS + kk * 16 + a_col));
#pragma unroll
                    for (int an = 0; an < 4; an++)
                        mma16816(acc[am][an], af, &bfr[2 * an]);
                }
            }
        }
    };

    // ---- Pass 1: Q tile -> qbuf (fp16) ----
    gemm_pass(g_AB, Wq);
    {
        const float* bh = bq + h * 128;
#pragma unroll
        for (int am = 0; am < 4; am++) {
#pragma unroll
            for (int an = 0; an < 4; an++) {
                int r0 = wm + am * 16 + tr;
                int cl = wn + an * 8 + tc;
                float* a = acc[am][an];
                float2 bb = *reinterpret_cast<const float2*>(&bh[cl]);
                *reinterpret_cast<__half2*>(&qbuf[r0 * QLD + cl]) =
                    __floats2half2_rn(a[0] + bb.x, a[1] + bb.y);
                *reinterpret_cast<__half2*>(&qbuf[(r0 + 8) * QLD + cl]) =
                    __floats2half2_rn(a[2] + bb.x, a[3] + bb.y);
            }
        }
    }
    __syncthreads();   // stage buffers free + rowsum init visible

    // ---- Pass 2: DK tile; dot against qbuf ----
    gemm_pass(g_D, Wk);
    {
#pragma unroll
        for (int am = 0; am < 4; am++) {
            float p0 = 0.f, p1 = 0.f;
            int r0 = wm + am * 16 + tr;
#pragma unroll
            for (int an = 0; an < 4; an++) {
                int cl = wn + an * 8 + tc;
                float* a = acc[am][an];
                float2 q0 = __half22float2(*reinterpret_cast<const __half2*>(&qbuf[r0 * QLD + cl]));
                float2 q1 = __half22float2(*reinterpret_cast<const __half2*>(&qbuf[(r0 + 8) * QLD + cl]));
                p0 += a[0] * q0.x + a[1] * q0.y;
                p1 += a[2] * q1.x + a[3] * q1.y;
            }
            // reduce over the 4 tc-lanes sharing this row
            p0 += __shfl_xor_sync(0xffffffffu, p0, 1);
            p0 += __shfl_xor_sync(0xffffffffu, p0, 2);
            p1 += __shfl_xor_sync(0xffffffffu, p1, 1);
            p1 += __shfl_xor_sync(0xffffffffu, p1, 2);
            if ((lane & 3) == 0) {
                atomicAdd(&rowsum[r0], p0);
                atomicAdd(&rowsum[r0 + 8], p1);
            }
        }
    }
    __syncthreads();

    if (tid < 128) {
        const float scale = 0.08838834764831845f;   // 1/sqrt(128)
        float a0 = 1.f / (1.f + __expf(-scale * rowsum[tid]));
        g_attw[(size_t)(bm + tid) * H_ + h] = a0;
    }
}

// ---------------------------------------------------------------------------
// Fused V-projection + attention combine (fragment-mix, 4Mx2N warp grid):
//   ctx[:, h*128:(h+1)*128] = (a0_h*img + (1-a0_h)*sig) * Wv_h^T + bv_h
// ---------------------------------------------------------------------------
constexpr int V_STGH = 3 * A_STG;                    // img + sig + B
constexpr int V_SMEM = 2 * V_STGH * (int)sizeof(__half);  // 110592

__global__ __launch_bounds__(256, 2) void k_vgemm(const float* __restrict__ bv) {
    extern __shared__ __half smem[];

    const int h  = blockIdx.x;
    const int bm = blockIdx.y * BM;
    const int tid  = threadIdx.x;
    const int warp = tid >> 5;
    const int lane = tid & 31;
    const int wm   = (warp & 3) * 32;      // 4 M-warps
    const int wn   = (warp >> 2) * 64;     // 2 N-warps

    const __half* Aimg = g_AB;
    const __half* Asig = g_AB + (size_t)B_ * E_;
    const __half* W    = g_Wv + (size_t)h * 128 * KDIM;

    float acc[2][8][4];
#pragma unroll
    for (int i = 0; i < 2; i++)
#pragma unroll
        for (int j = 0; j < 8; j++)
#pragma unroll
            for (int l = 0; l < 4; l++) acc[i][j][l] = 0.f;

    uint32_t c0[2][2], c1[2][2];
    {
        const int g = lane >> 2;
#pragma unroll
        for (int am = 0; am < 2; am++) {
            int r0 = bm + wm + am * 16 + g;
            float ca = g_attw[(size_t)r0 * H_ + h];
            float cb = g_attw[(size_t)(r0 + 8) * H_ + h];
            __half2 t;
            t = __float2half2_rn(ca);       c0[am][0] = *reinterpret_cast<uint32_t*>(&t);
            t = __float2half2_rn(1.f - ca); c1[am][0] = *reinterpret_cast<uint32_t*>(&t);
            t = __float2half2_rn(cb);       c0[am][1] = *reinterpret_cast<uint32_t*>(&t);
            t = __float2half2_rn(1.f - cb); c1[am][1] = *reinterpret_cast<uint32_t*>(&t);
        }
    }

    auto load_stage = [&](int stage, int kt) {
        const int k0 = kt * BK;
        __half* si = smem + stage * V_STGH;
        __half* ss = si + A_STG;
        __half* sb = si + 2 * A_STG;
#pragma unroll
        for (int i = 0; i < 12; i++) {
            int id = tid + i * 256;
            int row = (id & 1023) >> 3, seg = id & 7;
            if (id < 1024)
                cp16(smem_u32(si + row * LDS + seg * 8),
                     Aimg + (size_t)(bm + row) * KDIM + k0 + seg * 8);
            else if (id < 2048)
                cp16(smem_u32(ss + row * LDS + seg * 8),
                     Asig + (size_t)(bm + row) * KDIM + k0 + seg * 8);
            else
                cp16(smem_u32(sb + row * LDS + seg * 8),
                     W + (size_t)row * KDIM + k0 + seg * 8);
        }
    };

    load_stage(0, 0);
    cp_commit();

    const int a_row = (lane & 15);
    const int a_col = (lane >> 4) * 8;
    const int b_row = ((lane >> 4) << 3) + (lane & 7);
    const int b_col = ((lane >> 3) & 1) * 8;

    for (int kt = 0; kt < KT; kt++) {
        cp_wait<0>();
        __syncthreads();

        if (kt + 1 < KT) load_stage((kt + 1) & 1, kt + 1);
        cp_commit();

        const __half* ai = smem + (kt & 1) * V_STGH;
        const __half* as = ai + A_STG;
        const __half* bs = ai + 2 * A_STG;

#pragma unroll
        for (int kk = 0; kk < 4; kk++) {
            uint32_t bfr[16];
#pragma unroll
            for (int p = 0; p < 4; p++) {
                uint32_t t[4];
                int r = wn + p * 16 + b_row;
                ldmatrix_x4(t, smem_u32(bs + r * LDS + kk * 16 + b_col));
                bfr[4 * p + 0] = t[0]; bfr[4 * p + 1] = t[1];
                bfr[4 * p + 2] = t[2]; bfr[4 * p + 3] = t[3];
            }
#pragma unroll
            for (int am = 0; am < 2; am++) {
                uint32_t fi[4], fs[4], af[4];
                int r = wm + am * 16 + a_row;
                ldmatrix_x4(fi, smem_u32(ai + r * LDS + kk * 16 + a_col));
                ldmatrix_x4(fs, smem_u32(as + r * LDS + kk * 16 + a_col));
#pragma unroll
                for (int j = 0; j < 4; j++) {
                    const int half_sel = j & 1;
                    __half2 i2 = *reinterpret_cast<__half2*>(&fi[j]);
                    __half2 s2 = *reinterpret_cast<__half2*>(&fs[j]);
                    __half2 cc0 = *reinterpret_cast<__half2*>(&c0[am][half_sel]);
                    __half2 cc1 = *reinterpret_cast<__half2*>(&c1[am][half_sel]);
                    __half2 mx = __hfma2(i2, cc0, __hmul2(s2, cc1));
                    af[j] = *reinterpret_cast<uint32_t*>(&mx);
                }
#pragma unroll
                for (int an = 0; an < 8; an++)
                    mma16816(acc[am][an], af, &bfr[2 * an]);
            }
        }
    }

    const int tr = lane >> 2;
    const int tc = (lane & 3) * 2;
    const float* bh = bv + h * 128;
    __half* outH = g_ctx + h * 128;
#pragma unroll
    for (int am = 0; am < 2; am++) {
#pragma unroll
        for (int an = 0; an < 8; an++) {
            int row0 = bm + wm + am * 16 + tr;
            int cl   = wn + an * 8 + tc;
            float* a = acc[am][an];
            float2 bb = *reinterpret_cast<const float2*>(&bh[cl]);
            *reinterpret_cast<__half2*>(&outH[(size_t)row0 * 1024 + cl]) =
                __floats2half2_rn(a[0] + bb.x, a[1] + bb.y);
            *reinterpret_cast<__half2*>(&outH[(size_t)(row0 + 8) * 1024 + cl]) =
                __floats2half2_rn(a[2] + bb.x, a[3] + bb.y);
        }
    }
}

// ---------------------------------------------------------------------------
// O-projection: fused = ctx * Wo^T + bo + img(fp16)   -> g_fused (fp16)
// ---------------------------------------------------------------------------
__global__ __launch_bounds__(256, 2) void k_ogemm(const float* __restrict__ bo) {
    const int col0 = blockIdx.x * 128;
    const int bm   = blockIdx.y * BM;
    gemm_core<1>(g_ctx, g_Wo + (size_t)col0 * KDIM, g_fused + col0,
                 bo + col0, g_AB + col0, bm, 1024);
}

// ---------------------------------------------------------------------------
// LayerNorm: one warp per row of 1024 halfs (compute fp32, write fp32).
// ---------------------------------------------------------------------------
__global__ void k_layernorm(const __half* __restrict__ fused,
                            const float* __restrict__ gamma,
                            const float* __restrict__ beta,
                            float* __restrict__ out) {
    int row  = blockIdx.x * (blockDim.x >> 5) + (threadIdx.x >> 5);
    int lane = threadIdx.x & 31;
    if (row >= B_) return;

    const uint4* r4 = reinterpret_cast<const uint4*>(fused + (size_t)row * E_);
    float xs[32];
    float s = 0.f, sq = 0.f;
#pragma unroll
    for (int j = 0; j < 4; j++) {
        uint4 v = r4[lane + 32 * j];
        const __half2* h2 = reinterpret_cast<const __half2*>(&v);
#pragma unroll
        for (int t = 0; t < 4; t++) {
            float2 f = __half22float2(h2[t]);
            xs[j * 8 + t * 2]     = f.x;
            xs[j * 8 + t * 2 + 1] = f.y;
            s  += f.x + f.y;
            sq += f.x * f.x + f.y * f.y;
        }
    }
#pragma unroll
    for (int off = 16; off > 0; off >>= 1) {
        s  += __shfl_xor_sync(0xffffffffu, s,  off);
        sq += __shfl_xor_sync(0xffffffffu, sq, off);
    }
    float mean = s * (1.f / E_);
    float var  = sq * (1.f / E_) - mean * mean;
    float rstd = rsqrtf(var + 1e-5f);

    float4* o4 = reinterpret_cast<float4*>(out + (size_t)row * E_);
    const float4* g4 = reinterpret_cast<const float4*>(gamma);
    const float4* b4 = reinterpret_cast<const float4*>(beta);
#pragma unroll
    for (int j = 0; j < 4; j++) {
        int c4 = (lane + 32 * j) * 2;
#pragma unroll
        for (int q = 0; q < 2; q++) {
            float4 g = g4[c4 + q], bb = b4[c4 + q], r;
            const float* x = &xs[j * 8 + q * 4];
            r.x = (x[0] - mean) * rstd * g.x + bb.x;
            r.y = (x[1] - mean) * rstd * g.y + bb.y;
            r.z = (x[2] - mean) * rstd * g.z + bb.z;
            r.w = (x[3] - mean) * rstd * g.w + bb.w;
            o4[c4 + q] = r;
        }
    }
}

// ---------------------------------------------------------------------------
// kernel_launch
// ---------------------------------------------------------------------------
extern "C" void kernel_launch(void* const* d_in, const int* in_sizes, int n_in,
                              void* d_out, int out_size) {
    const float* img   = (const float*)d_in[0];
    const float* sig   = (const float*)d_in[1];
    const float* wq    = (const float*)d_in[2];
    const float* wk    = (const float*)d_in[3];
    const float* wv    = (const float*)d_in[4];
    const float* bq    = (const float*)d_in[5];
    const float* bk    = (const float*)d_in[6];   // unused: cancels in score diff
    const float* bv    = (const float*)d_in[7];
    const float* wo    = (const float*)d_in[8];
    const float* bo    = (const float*)d_in[9];
    const float* gamma = (const float*)d_in[10];
    const float* beta  = (const float*)d_in[11];
    float* out = (float*)d_out;
    (void)bk;

    void* pFused;
    cudaGetSymbolAddress(&pFused, g_fused);

    cudaFuncSetAttribute(k_qkscore, cudaFuncAttributeMaxDynamicSharedMemorySize, QS_SMEM);
    cudaFuncSetAttribute(k_vgemm,   cudaFuncAttributeMaxDynamicSharedMemorySize, V_SMEM);
    cudaFuncSetAttribute(k_ogemm,   cudaFuncAttributeMaxDynamicSharedMemorySize, SMEM_BYTES);

    // 1) conversions (+ img-sig diff)
    k_convert_all<<<CVT_TOT / 256, 256>>>(img, sig, wq, wk, wv, wo);

    // 2) fused Q + DK + scores -> g_attw (no Q/DK materialization)
    k_qkscore<<<dim3(H_, B_ / BM), 256, QS_SMEM>>>(bq);

    // 3) fused V-projection + combine -> ctx (4Mx2N fragment-mix)
    k_vgemm<<<dim3(H_, B_ / BM), 256, V_SMEM>>>(bv);

    // 4) fused = ctx * Wo^T + bo + img(fp16)  -> fp16
    k_ogemm<<<dim3(E_ / BN, B_ / BM), 256, SMEM_BYTES>>>(bo);

    // 5) LayerNorm (fp16 in, fp32 out)
    k_layernorm<<<B_ / 8, 256>>>((const __half*)pFused, gamma, beta, out);
}

// round 16
// speedup vs baseline: 1.3409x; 1.0122x over previous
#include <cuda_runtime.h>
#include <cuda_fp16.h>
#include <cstdint>

// Problem constants
constexpr int B_ = 16384;
constexpr int E_ = 1024;
constexpr int H_ = 8;
constexpr int D_ = 128;

// ---------------------------------------------------------------------------
// Scratch (static device globals: allocation-free, graph-capture safe)
// ---------------------------------------------------------------------------
__device__ __half g_AB[2u * B_ * E_];           // [image; signal] fp16   (64 MB)
__device__ __half g_D[(size_t)B_ * E_];         // img - sig (fp16)       (32 MB)
__device__ __half g_Wq[E_ * E_];
__device__ __half g_Wk[E_ * E_];
__device__ __half g_Wv[E_ * E_];
__device__ __half g_Wo[E_ * E_];
__device__ __half g_ctx[(size_t)B_ * E_];       //                        (32 MB)
__device__ __half g_fused[(size_t)B_ * E_];     // attn_out + residual    (32 MB)

// ---------------------------------------------------------------------------
// PTX helpers (sm_80-class only: cp.async / ldmatrix / mma.sync)
// ---------------------------------------------------------------------------
__device__ __forceinline__ uint32_t smem_u32(const void* p) {
    return (uint32_t)__cvta_generic_to_shared(p);
}
__device__ __forceinline__ void cp16(uint32_t s, const void* g) {
    asm volatile("cp.async.cg.shared.global [%0], [%1], 16;\n" :: "r"(s), "l"(g));
}
__device__ __forceinline__ void cp_commit() {
    asm volatile("cp.async.commit_group;\n");
}
template <int N>
__device__ __forceinline__ void cp_wait() {
    asm volatile("cp.async.wait_group %0;\n" :: "n"(N));
}
__device__ __forceinline__ void ldmatrix_x4(uint32_t* r, uint32_t addr) {
    asm volatile("ldmatrix.sync.aligned.m8n8.x4.shared.b16 {%0,%1,%2,%3}, [%4];\n"
                 : "=r"(r[0]), "=r"(r[1]), "=r"(r[2]), "=r"(r[3]) : "r"(addr));
}
__device__ __forceinline__ void mma16816(float* c, const uint32_t* a, const uint32_t* b) {
    asm volatile("mma.sync.aligned.m16n8k16.row.col.f32.f16.f16.f32 "
                 "{%0,%1,%2,%3}, {%4,%5,%6,%7}, {%8,%9}, {%0,%1,%2,%3};\n"
                 : "+f"(c[0]), "+f"(c[1]), "+f"(c[2]), "+f"(c[3])
                 : "r"(a[0]), "r"(a[1]), "r"(a[2]), "r"(a[3]), "r"(b[0]), "r"(b[1]));
}

// ---------------------------------------------------------------------------
// Conversion: inputs fp32->fp16 (+ diff), weights fp32->fp16
// ---------------------------------------------------------------------------
constexpr int N4  = (B_ * E_) / 4;            // 4194304 (paired img/sig)
constexpr int W4  = (4 * E_ * E_) / 4;        // 1048576
constexpr int CVT_TOT = N4 + W4;              // divisible by 256

__global__ void k_convert_all(const float* __restrict__ img, const float* __restrict__ sig,
                              const float* __restrict__ wq, const float* __restrict__ wk,
                              const float* __restrict__ wv, const float* __restrict__ wo) {
    int i = blockIdx.x * blockDim.x + threadIdx.x;
    if (i < N4) {
        float4 a = reinterpret_cast<const float4*>(img)[i];
        float4 b = reinterpret_cast<const float4*>(sig)[i];
        __half* di = g_AB + (size_t)4 * i;
        __half* ds = g_AB + (size_t)B_ * E_ + (size_t)4 * i;
        __half* dd = g_D + (size_t)4 * i;
        *reinterpret_cast<__half2*>(di)     = __floats2half2_rn(a.x, a.y);
        *reinterpret_cast<__half2*>(di + 2) = __floats2half2_rn(a.z, a.w);
        *reinterpret_cast<__half2*>(ds)     = __floats2half2_rn(b.x, b.y);
        *reinterpret_cast<__half2*>(ds + 2) = __floats2half2_rn(b.z, b.w);
        *reinterpret_cast<__half2*>(dd)     = __floats2half2_rn(a.x - b.x, a.y - b.y);
        *reinterpret_cast<__half2*>(dd + 2) = __floats2half2_rn(a.z - b.z, a.w - b.w);
    } else {
        int j = i - N4;
        const int per = (E_ * E_) / 4;
        int m = j / per;
        int t = j - m * per;
        const float* src;
        __half* dst;
        if (m == 0)      { src = wq; dst = g_Wq; }
        else if (m == 1) { src = wk; dst = g_Wk; }
        else if (m == 2) { src = wv; dst = g_Wv; }
        else             { src = wo; dst = g_Wo; }
        float4 v = reinterpret_cast<const float4*>(src)[t];
        dst += (size_t)4 * t;
        *reinterpret_cast<__half2*>(dst)     = __floats2half2_rn(v.x, v.y);
        *reinterpret_cast<__half2*>(dst + 2) = __floats2half2_rn(v.z, v.w);
    }
}

// ---------------------------------------------------------------------------
// Shared tiling constants
// ---------------------------------------------------------------------------
constexpr int BM = 128, BN = 128, BK = 64, STAGES = 3;
constexpr int KDIM = 1024, KT = KDIM / BK;           // 16
constexpr int LDS = BK + 8;                          // 72 halfs / 144B row
constexpr int A_STG = BM * LDS;                      // 9216 halfs
constexpr int STG   = 2 * A_STG;
constexpr int SMEM_BYTES = STAGES * STG * (int)sizeof(__half);   // 110592

// ---------------------------------------------------------------------------
// GEMM core (ogemm): half out = acc + bias[cl] + residH (fp16)
// ---------------------------------------------------------------------------
__device__ __forceinline__ void gemm_core(
    const __half* __restrict__ A,
    const __half* __restrict__ W,
    __half* __restrict__ outH,
    const float* __restrict__ bias,
    const __half* __restrict__ residH,
    int bm, int ldOut)
{
    extern __shared__ __half smem[];

    const int tid  = threadIdx.x;
    const int warp = tid >> 5;
    const int lane = tid & 31;
    const int wm   = (warp & 1) * 64;
    const int wn   = (warp >> 1) * 32;

    float acc[4][4][4];
#pragma unroll
    for (int i = 0; i < 4; i++)
#pragma unroll
        for (int j = 0; j < 4; j++)
#pragma unroll
            for (int l = 0; l < 4; l++) acc[i][j][l] = 0.f;

    auto load_stage = [&](int stage, int kt) {
        const int k0 = kt * BK;
        __half* sa = smem + stage * STG;
        __half* sb = sa + A_STG;
#pragma unroll
        for (int i = 0; i < 8; i++) {
            int id = tid + i * 256;
            if (id < 1024) {
                int row = id >> 3, seg = id & 7;
                cp16(smem_u32(sa + row * LDS + seg * 8),
                     A + (size_t)(bm + row) * KDIM + k0 + seg * 8);
            } else {
                id -= 1024;
                int row = id >> 3, seg = id & 7;
                cp16(smem_u32(sb + row * LDS + seg * 8),
                     W + (size_t)row * KDIM + k0 + seg * 8);
            }
        }
    };

#pragma unroll
    for (int s = 0; s < STAGES - 1; s++) { load_stage(s, s); cp_commit(); }

    const int a_row = (lane & 15);
    const int a_col = (lane >> 4) * 8;
    const int b_row = ((lane >> 4) << 3) + (lane & 7);
    const int b_col = ((lane >> 3) & 1) * 8;

    for (int kt = 0; kt < KT; kt++) {
        cp_wait<STAGES - 2>();
        __syncthreads();

        if (kt + STAGES - 1 < KT) load_stage((kt + STAGES - 1) % STAGES, kt + STAGES - 1);
        cp_commit();

        const __half* as = smem + (kt % STAGES) * STG;
        const __half* bs = as + A_STG;

#pragma unroll
        for (int kk = 0; kk < 4; kk++) {
            uint32_t bfr[8];
#pragma unroll
            for (int p = 0; p < 2; p++) {
                uint32_t t[4];
                int r = wn + p * 16 + b_row;
                ldmatrix_x4(t, smem_u32(bs + r * LDS + kk * 16 + b_col));
                bfr[4 * p + 0] = t[0]; bfr[4 * p + 1] = t[1];
                bfr[4 * p + 2] = t[2]; bfr[4 * p + 3] = t[3];
            }
#pragma unroll
            for (int am = 0; am < 4; am++) {
                uint32_t af[4];
                int r = wm + am * 16 + a_row;
                ldmatrix_x4(af, smem_u32(as + r * LDS + kk * 16 + a_col));
#pragma unroll
                for (int an = 0; an < 4; an++)
                    mma16816(acc[am][an], af, &bfr[2 * an]);
            }
        }
    }

    const int tr = lane >> 2;
    const int tc = (lane & 3) * 2;
#pragma unroll
    for (int am = 0; am < 4; am++) {
#pragma unroll
        for (int an = 0; an < 4; an++) {
            int row0 = bm + wm + am * 16 + tr;
            int cl   = wn + an * 8 + tc;
            float* a = acc[am][an];
            float2 bb = *reinterpret_cast<const float2*>(&bias[cl]);
            size_t i0 = (size_t)row0 * ldOut + cl;
            size_t i1 = (size_t)(row0 + 8) * ldOut + cl;
            float2 r0 = __half22float2(*reinterpret_cast<const __half2*>(&residH[i0]));
            float2 r1 = __half22float2(*reinterpret_cast<const __half2*>(&residH[i1]));
            *reinterpret_cast<__half2*>(&outH[i0]) =
                __floats2half2_rn(a[0] + bb.x + r0.x, a[1] + bb.y + r0.y);
            *reinterpret_cast<__half2*>(&outH[i1]) =
                __floats2half2_rn(a[2] + bb.x + r1.x, a[3] + bb.y + r1.y);
        }
    }
}

// ---------------------------------------------------------------------------
// Fully fused attention kernel. Grid (H_, 128), 256 threads.
// Pass 1: Qtile = img * Wq_h^T + bq -> smem qbuf (fp16)       [2Mx4N warps]
// Pass 2: DKtile = diff * Wk_h^T; fragment-dot vs qbuf ->
//         rowsum[128]; a0 = sigmoid(scale*rowsum) (in smem)   [2Mx4N warps]
// Pass 3: ctx_h = sig*Wv_h^T + bv + a0 .* (diff*Wv_h^T)
//         = mix(sig + a0*diff) GEMM, fragment-mix 1xHFMA2     [4Mx2N warps]
// a0 never leaves shared memory.
// ---------------------------------------------------------------------------
constexpr int QLD = 136;
constexpr int V_STGH = 3 * A_STG;                    // diff + sig + Wv
constexpr int QS_BYTES = (2 * STG + 128 * QLD) * (int)sizeof(__half) + 512;
constexpr int VP_BYTES = 2 * V_STGH * (int)sizeof(__half);
constexpr int FUSED_SMEM = (QS_BYTES > VP_BYTES ? QS_BYTES : VP_BYTES) + 512; // 111616

__global__ __launch_bounds__(256, 2) void k_attn(const float* __restrict__ bq,
                                                 const float* __restrict__ bv) {
    extern __shared__ __half smem[];
    __half* qbuf   = smem + 2 * STG;
    float*  rowsum = reinterpret_cast<float*>(smem + 2 * STG + 128 * QLD);

    const int h  = blockIdx.x;
    const int bm = blockIdx.y * BM;
    const int tid  = threadIdx.x;
    const int warp = tid >> 5;
    const int lane = tid & 31;

    if (tid < 128) rowsum[tid] = 0.f;

    const __half* Adiff = g_D;
    const __half* Asig  = g_AB + (size_t)B_ * E_;
    const __half* Wq = g_Wq + (size_t)h * 128 * KDIM;
    const __half* Wk = g_Wk + (size_t)h * 128 * KDIM;
    const __half* Wv = g_Wv + (size_t)h * 128 * KDIM;

    const int a_row = (lane & 15);
    const int a_col = (lane >> 4) * 8;
    const int b_row = ((lane >> 4) << 3) + (lane & 7);
    const int b_col = ((lane >> 3) & 1) * 8;
    const int tr = lane >> 2;
    const int tc = (lane & 3) * 2;

    // ======================= Phase A: Q + DK + score =======================
    {
        const int wm = (warp & 1) * 64;
        const int wn = (warp >> 1) * 32;
        float acc[4][4][4];

        auto load_stage = [&](int stage, int kt, const __half* A, const __half* W) {
            const int k0 = kt * BK;
            __half* sa = smem + stage * STG;
            __half* sb = sa + A_STG;
#pragma unroll
            for (int i = 0; i < 8; i++) {
                int id = tid + i * 256;
                if (id < 1024) {
                    int row = id >> 3, seg = id & 7;
                    cp16(smem_u32(sa + row * LDS + seg * 8),
                         A + (size_t)(bm + row) * KDIM + k0 + seg * 8);
                } else {
                    id -= 1024;
                    int row = id >> 3, seg = id & 7;
                    cp16(smem_u32(sb + row * LDS + seg * 8),
                         W + (size_t)row * KDIM + k0 + seg * 8);
                }
            }
        };

        auto gemm_pass = [&](const __half* A, const __half* W) {
#pragma unroll
            for (int i = 0; i < 4; i++)
#pragma unroll
                for (int j = 0; j < 4; j++)
#pragma unroll
                    for (int l = 0; l < 4; l++) acc[i][j][l] = 0.f;

            load_stage(0, 0, A, W);
            cp_commit();

            for (int kt = 0; kt < KT; kt++) {
                cp_wait<0>();
                __syncthreads();

                if (kt + 1 < KT) load_stage((kt + 1) & 1, kt + 1, A, W);
                cp_commit();

                const __half* as = smem + (kt & 1) * STG;
                const __half* bs = as + A_STG;

#pragma unroll
                for (int kk = 0; kk < 4; kk++) {
                    uint32_t bfr[8];
#pragma unroll
                    for (int p = 0; p < 2; p++) {
                        uint32_t t[4];
                        int r = wn + p * 16 + b_row;
                        ldmatrix_x4(t, smem_u32(bs + r * LDS + kk * 16 + b_col));
                        bfr[4 * p + 0] = t[0]; bfr[4 * p + 1] = t[1];
                        bfr[4 * p + 2] = t[2]; bfr[4 * p + 3] = t[3];
                    }
#pragma unroll
                    for (int am = 0; am < 4; am++) {
                        uint32_t af[4];
                        int r = wm + am * 16 + a_row;
                        ldmatrix_x4(af, smem_u32(as + r * LDS + kk * 16 + a_col));
#pragma unroll
                        for (int an = 0; an < 4; an++)
                            mma16816(acc[am][an], af, &bfr[2 * an]);
                    }
                }
            }
        };

        // Pass 1: Q -> qbuf
        gemm_pass(g_AB, Wq);
        {
            const float* bh = bq + h * 128;
#pragma unroll
            for (int am = 0; am < 4; am++) {
#pragma unroll
                for (int an = 0; an < 4; an++) {
                    int r0 = wm + am * 16 + tr;
                    int cl = wn + an * 8 + tc;
                    float* a = acc[am][an];
                    float2 bb = *reinterpret_cast<const float2*>(&bh[cl]);
                    *reinterpret_cast<__half2*>(&qbuf[r0 * QLD + cl]) =
                        __floats2half2_rn(a[0] + bb.x, a[1] + bb.y);
                    *reinterpret_cast<__half2*>(&qbuf[(r0 + 8) * QLD + cl]) =
                        __floats2half2_rn(a[2] + bb.x, a[3] + bb.y);
                }
            }
        }
        __syncthreads();

        // Pass 2: DK; fragment-dot vs qbuf
        gemm_pass(Adiff, Wk);
#pragma unroll
        for (int am = 0; am < 4; am++) {
            float p0 = 0.f, p1 = 0.f;
            int r0 = wm + am * 16 + tr;
#pragma unroll
            for (int an = 0; an < 4; an++) {
                int cl = wn + an * 8 + tc;
                float* a = acc[am][an];
                float2 q0 = __half22float2(*reinterpret_cast<const __half2*>(&qbuf[r0 * QLD + cl]));
                float2 q1 = __half22float2(*reinterpret_cast<const __half2*>(&qbuf[(r0 + 8) * QLD + cl]));
                p0 += a[0] * q0.x + a[1] * q0.y;
                p1 += a[2] * q1.x + a[3] * q1.y;
            }
            p0 += __shfl_xor_sync(0xffffffffu, p0, 1);
            p0 += __shfl_xor_sync(0xffffffffu, p0, 2);
            p1 += __shfl_xor_sync(0xffffffffu, p1, 1);
            p1 += __shfl_xor_sync(0xffffffffu, p1, 2);
            if ((lane & 3) == 0) {
                atomicAdd(&rowsum[r0], p0);
                atomicAdd(&rowsum[r0 + 8], p1);
            }
        }
        __syncthreads();

        if (tid < 128) {
            const float scale = 0.08838834764831845f;   // 1/sqrt(128)
            rowsum[tid] = 1.f / (1.f + __expf(-scale * rowsum[tid]));   // a0, local rows
        }
        __syncthreads();
    }

    // ======================= Phase B: V-projection + mix ====================
    {
        const int wm = (warp & 3) * 32;      // 4 M-warps
        const int wn = (warp >> 2) * 64;     // 2 N-warps

        // per-row a0 coefficients -> registers BEFORE smem is overwritten
        uint32_t ch[2][2];
        {
            const int g = lane >> 2;
#pragma unroll
            for (int am = 0; am < 2; am++) {
                int r0 = wm + am * 16 + g;   // local row
                __half2 t;
                t = __float2half2_rn(rowsum[r0]);     ch[am][0] = *reinterpret_cast<uint32_t*>(&t);
                t = __float2half2_rn(rowsum[r0 + 8]); ch[am][1] = *reinterpret_cast<uint32_t*>(&t);
            }
        }
        __syncthreads();   // coefficient reads done; smem free for pipeline

        float acc[2][8][4];
#pragma unroll
        for (int i = 0; i < 2; i++)
#pragma unroll
            for (int j = 0; j < 8; j++)
#pragma unroll
                for (int l = 0; l < 4; l++) acc[i][j][l] = 0.f;

        auto load_stage = [&](int stage, int kt) {
            const int k0 = kt * BK;
            __half* sd = smem + stage * V_STGH;
            __half* ss = sd + A_STG;
            __half* sb = sd + 2 * A_STG;
#pragma unroll
            for (int i = 0; i < 12; i++) {
                int id = tid + i * 256;
                int row = (id & 1023) >> 3, seg = id & 7;
                if (id < 1024)
                    cp16(smem_u32(sd + row * LDS + seg * 8),
                         Adiff + (size_t)(bm + row) * KDIM + k0 + seg * 8);
                else if (id < 2048)
                    cp16(smem_u32(ss + row * LDS + seg * 8),
                         Asig + (size_t)(bm + row) * KDIM + k0 + seg * 8);
                else
                    cp16(smem_u32(sb + row * LDS + seg * 8),
                         Wv + (size_t)row * KDIM + k0 + seg * 8);
            }
        };

        load_stage(0, 0);
        cp_commit();

        for (int kt = 0; kt < KT; kt++) {
            cp_wait<0>();
            __syncthreads();

            if (kt + 1 < KT) load_stage((kt + 1) & 1, kt + 1);
            cp_commit();

            const __half* sd = smem + (kt & 1) * V_STGH;
            const __half* ss = sd + A_STG;
            const __half* sb = sd + 2 * A_STG;

#pragma unroll
            for (int kk = 0; kk < 4; kk++) {
                uint32_t bfr[16];
#pragma unroll
                for (int p = 0; p < 4; p++) {
                    uint32_t t[4];
                    int r = wn + p * 16 + b_row;
                    ldmatrix_x4(t, smem_u32(sb + r * LDS + kk * 16 + b_col));
                    bfr[4 * p + 0] = t[0]; bfr[4 * p + 1] = t[1];
                    bfr[4 * p + 2] = t[2]; bfr[4 * p + 3] = t[3];
                }
#pragma unroll
                for (int am = 0; am < 2; am++) {
                    uint32_t fd[4], fs[4], af[4];
                    int r = wm + am * 16 + a_row;
                    ldmatrix_x4(fd, smem_u32(sd + r * LDS + kk * 16 + a_col));
                    ldmatrix_x4(fs, smem_u32(ss + r * LDS + kk * 16 + a_col));
#pragma unroll
                    for (int j = 0; j < 4; j++) {
                        const int half_sel = j & 1;
                        __half2 d2 = *reinterpret_cast<__half2*>(&fd[j]);
                        __half2 s2 = *reinterpret_cast<__half2*>(&fs[j]);
                        __half2 cc = *reinterpret_cast<__half2*>(&ch[am][half_sel]);
                        __half2 mx = __hfma2(d2, cc, s2);   // sig + a0*diff
                        af[j] = *reinterpret_cast<uint32_t*>(&mx);
                    }
#pragma unroll
                    for (int an = 0; an < 8; an++)
                        mma16816(acc[am][an], af, &bfr[2 * an]);
                }
            }
        }

        const float* bh = bv + h * 128;
        __half* outH = g_ctx + h * 128;
#pragma unroll
        for (int am = 0; am < 2; am++) {
#pragma unroll
            for (int an = 0; an < 8; an++) {
                int row0 = bm + wm + am * 16 + tr;
                int cl   = wn + an * 8 + tc;
                float* a = acc[am][an];
                float2 bb = *reinterpret_cast<const float2*>(&bh[cl]);
                *reinterpret_cast<__half2*>(&outH[(size_t)row0 * 1024 + cl]) =
                    __floats2half2_rn(a[0] + bb.x, a[1] + bb.y);
                *reinterpret_cast<__half2*>(&outH[(size_t)(row0 + 8) * 1024 + cl]) =
                    __floats2half2_rn(a[2] + bb.x, a[3] + bb.y);
            }
        }
    }
}

// ---------------------------------------------------------------------------
// O-projection: fused = ctx * Wo^T + bo + img(fp16)   -> g_fused (fp16)
// ---------------------------------------------------------------------------
__global__ __launch_bounds__(256, 2) void k_ogemm(const float* __restrict__ bo) {
    const int col0 = blockIdx.x * 128;
    const int bm   = blockIdx.y * BM;
    gemm_core(g_ctx, g_Wo + (size_t)col0 * KDIM, g_fused + col0,
              bo + col0, g_AB + col0, bm, 1024);
}

// ---------------------------------------------------------------------------
// LayerNorm: one warp per row of 1024 halfs (compute fp32, write fp32).
// ---------------------------------------------------------------------------
__global__ void k_layernorm(const __half* __restrict__ fused,
                            const float* __restrict__ gamma,
                            const float* __restrict__ beta,
                            float* __restrict__ out) {
    int row  = blockIdx.x * (blockDim.x >> 5) + (threadIdx.x >> 5);
    int lane = threadIdx.x & 31;
    if (row >= B_) return;

    const uint4* r4 = reinterpret_cast<const uint4*>(fused + (size_t)row * E_);
    float xs[32];
    float s = 0.f, sq = 0.f;
#pragma unroll
    for (int j = 0; j < 4; j++) {
        uint4 v = r4[lane + 32 * j];
        const __half2* h2 = reinterpret_cast<const __half2*>(&v);
#pragma unroll
        for (int t = 0; t < 4; t++) {
            float2 f = __half22float2(h2[t]);
            xs[j * 8 + t * 2]     = f.x;
            xs[j * 8 + t * 2 + 1] = f.y;
            s  += f.x + f.y;
            sq += f.x * f.x + f.y * f.y;
        }
    }
#pragma unroll
    for (int off = 16; off > 0; off >>= 1) {
        s  += __shfl_xor_sync(0xffffffffu, s,  off);
        sq += __shfl_xor_sync(0xffffffffu, sq, off);
    }
    float mean = s * (1.f / E_);
    float var  = sq * (1.f / E_) - mean * mean;
    float rstd = rsqrtf(var + 1e-5f);

    float4* o4 = reinterpret_cast<float4*>(out + (size_t)row * E_);
    const float4* g4 = reinterpret_cast<const float4*>(gamma);
    const float4* b4 = reinterpret_cast<const float4*>(beta);
#pragma unroll
    for (int j = 0; j < 4; j++) {
        int c4 = (lane + 32 * j) * 2;
#pragma unroll
        for (int q = 0; q < 2; q++) {
            float4 g = g4[c4 + q], bb = b4[c4 + q], r;
            const float* x = &xs[j * 8 + q * 4];
            r.x = (x[0] - mean) * rstd * g.x + bb.x;
            r.y = (x[1] - mean) * rstd * g.y + bb.y;
            r.z = (x[2] - mean) * rstd * g.z + bb.z;
            r.w = (x[3] - mean) * rstd * g.w + bb.w;
            o4[c4 + q] = r;
        }
    }
}

// ---------------------------------------------------------------------------
// kernel_launch
// ---------------------------------------------------------------------------
extern "C" void kernel_launch(void* const* d_in, const int* in_sizes, int n_in,
                              void* d_out, int out_size) {
    const float* img   = (const float*)d_in[0];
    const float* sig   = (const float*)d_in[1];
    const float* wq    = (const float*)d_in[2];
    const float* wk    = (const float*)d_in[3];
    const float* wv    = (const float*)d_in[4];
    const float* bq    = (const float*)d_in[5];
    const float* bk    = (const float*)d_in[6];   // unused: cancels in score diff
    const float* bv    = (const float*)d_in[7];
    const float* wo    = (const float*)d_in[8];
    const float* bo    = (const float*)d_in[9];
    const float* gamma = (const float*)d_in[10];
    const float* beta  = (const float*)d_in[11];
    float* out = (float*)d_out;
    (void)bk;

    void* pFused;
    cudaGetSymbolAddress(&pFused, g_fused);

    cudaFuncSetAttribute(k_attn,  cudaFuncAttributeMaxDynamicSharedMemorySize, FUSED_SMEM);
    cudaFuncSetAttribute(k_ogemm, cudaFuncAttributeMaxDynamicSharedMemorySize, SMEM_BYTES);

    // 1) conversions (+ img-sig diff)
    k_convert_all<<<CVT_TOT / 256, 256>>>(img, sig, wq, wk, wv, wo);

    // 2) fully fused attention: Q + DK + score + V-mix -> ctx
    k_attn<<<dim3(H_, B_ / BM), 256, FUSED_SMEM>>>(bq, bv);

    // 3) fused = ctx * Wo^T + bo + img(fp16)  -> fp16
    k_ogemm<<<dim3(E_ / BN, B_ / BM), 256, SMEM_BYTES>>>(bo);

    // 4) LayerNorm (fp16 in, fp32 out)
    k_layernorm<<<B_ / 8, 256>>>((const __half*)pFused, gamma, beta, out);
}